// round 6
// baseline (speedup 1.0000x reference)
#include <cuda_runtime.h>
#include <math.h>
#include <stdint.h>

#define DM 3072
#define BB 2
#define SSEQ 1024
#define NH 24
#define HD 128
#define MROWS (BB*SSEQ)   // 2048

// Scratch (device globals: no allocations allowed)
__device__ float g_q[MROWS*DM];
__device__ float g_k[MROWS*DM];
__device__ float g_v[MROWS*DM];
__device__ float g_ao[MROWS*DM];

__device__ __forceinline__ uint32_t smem_u32(const void* p) {
    uint32_t a;
    asm("{ .reg .u64 t; cvta.to.shared.u64 t, %1; cvt.u32.u64 %0, t; }"
        : "=r"(a) : "l"(p));
    return a;
}

__device__ __forceinline__ uint32_t f2tf32(float x) {
    uint32_t r;
    asm("cvt.rna.tf32.f32 %0, %1;" : "=r"(r) : "f"(x));
    return r;
}

__device__ __forceinline__ void mma_tf32(float c[4],
    uint32_t a0, uint32_t a1, uint32_t a2, uint32_t a3,
    uint32_t b0, uint32_t b1)
{
    asm volatile(
        "mma.sync.aligned.m16n8k8.row.col.f32.tf32.tf32.f32 "
        "{%0,%1,%2,%3}, {%4,%5,%6,%7}, {%8,%9}, {%0,%1,%2,%3};"
        : "+f"(c[0]), "+f"(c[1]), "+f"(c[2]), "+f"(c[3])
        : "r"(a0), "r"(a1), "r"(a2), "r"(a3), "r"(b0), "r"(b1));
}

__device__ __forceinline__ void ldsm_x4(
    uint32_t& r0, uint32_t& r1, uint32_t& r2, uint32_t& r3, uint32_t addr)
{
    asm volatile("ldmatrix.sync.aligned.m8n8.x4.shared.b16 {%0,%1,%2,%3}, [%4];"
        : "=r"(r0), "=r"(r1), "=r"(r2), "=r"(r3) : "r"(addr));
}

// ---------------------------------------------------------------------------
// tf32 GEMM, CTA tile 128m x 256n x 16k, 8 warps each 64x64, double-buffered.
// Y[m,n] = sum_k X[m,k] * W[n,k].  Fused over up to 3 weights via blockIdx.x.
// Smem layout (words): A0 @0 (128*20), A1 @2560, B0 @5120 (256*20), B1 @10240.
// ---------------------------------------------------------------------------
#define PADK 20
#define A_BUF_BYTES (128 * PADK * 4)           // 10240
#define B_BASE_BYTES (2 * A_BUF_BYTES)         // 20480
#define B_BUF_BYTES (256 * PADK * 4)           // 20480
#define GEMM_SMEM (B_BASE_BYTES + 2 * B_BUF_BYTES)  // 61440

__global__ __launch_bounds__(256, 1) void tf32_gemm_kernel(
    const float* __restrict__ X,
    const float* __restrict__ Wa, const float* __restrict__ Wb, const float* __restrict__ Wc,
    float* __restrict__ Ya, float* __restrict__ Yb, float* __restrict__ Yc,
    int ntiles)   // n-tiles per weight matrix (DM/256 = 12)
{
    extern __shared__ uint32_t sm[];
    const uint32_t smb = smem_u32(sm);

    const int t    = threadIdx.x;
    const int lane = t & 31;
    const int w    = t >> 5;
    const int warp_m = (w & 1) * 64;         // 0,64
    const int warp_n = (w >> 1) * 64;        // 0,64,128,192
    const int bx   = blockIdx.x;
    const int wsel = bx / ntiles;
    const float* W = (wsel == 0) ? Wa : ((wsel == 1) ? Wb : Wc);
    float*       Y = (wsel == 0) ? Ya : ((wsel == 1) ? Yb : Yc);
    const int bm = blockIdx.y * 128;
    const int bn = (bx - wsel * ntiles) * 256;

    // Global load mapping: A row t>>1, k-half (t&1)*8; B row t, 16 k.
    const int arow = t >> 1;
    const int ac8  = (t & 1) * 8;
    const float* xp = X + (size_t)(bm + arow) * DM + ac8;
    const float* wp = W + (size_t)(bn + t) * DM;

    // ldmatrix per-lane base addresses (buffer 0, kstep 0)
    const int l7 = lane & 7;
    const int aArow = warp_m + ((lane >> 3) & 1) * 8 + l7;
    const int aAk   = (lane >> 4) * 4;
    uint32_t aA[4];
    #pragma unroll
    for (int mi = 0; mi < 4; mi++)
        aA[mi] = smb + (uint32_t)((aArow + mi * 16) * PADK + aAk) * 4u;
    const int aBcol = warp_n + (lane >> 4) * 8 + l7;
    const int aBk   = ((lane >> 3) & 1) * 4;
    uint32_t aB[4];
    #pragma unroll
    for (int np = 0; np < 4; np++)
        aB[np] = smb + (uint32_t)B_BASE_BYTES
               + (uint32_t)((aBcol + np * 16) * PADK + aBk) * 4u;

    float c[4][8][4];
    #pragma unroll
    for (int mi = 0; mi < 4; mi++)
        #pragma unroll
        for (int ni = 0; ni < 8; ni++)
            #pragma unroll
            for (int j = 0; j < 4; j++) c[mi][ni][j] = 0.f;

    const int qd = lane >> 2;
    const int qk = lane & 3;
    const int NKT = DM / 16;   // 192

    // Store a k-tile (registers -> smem, tf32-converted, STS.128)
    #define GSTORE(buf) do { \
        uint32_t* Ab = sm + (buf) * (A_BUF_BYTES/4); \
        uint32_t* Bb = sm + (B_BASE_BYTES/4) + (buf) * (B_BUF_BYTES/4); \
        uint4 u0 = {f2tf32(ax0.x), f2tf32(ax0.y), f2tf32(ax0.z), f2tf32(ax0.w)}; \
        uint4 u1 = {f2tf32(ax1.x), f2tf32(ax1.y), f2tf32(ax1.z), f2tf32(ax1.w)}; \
        *(uint4*)&Ab[arow*PADK + ac8]     = u0; \
        *(uint4*)&Ab[arow*PADK + ac8 + 4] = u1; \
        uint4 v0 = {f2tf32(bx0.x), f2tf32(bx0.y), f2tf32(bx0.z), f2tf32(bx0.w)}; \
        uint4 v1 = {f2tf32(bx1.x), f2tf32(bx1.y), f2tf32(bx1.z), f2tf32(bx1.w)}; \
        uint4 v2 = {f2tf32(bx2.x), f2tf32(bx2.y), f2tf32(bx2.z), f2tf32(bx2.w)}; \
        uint4 v3 = {f2tf32(bx3.x), f2tf32(bx3.y), f2tf32(bx3.z), f2tf32(bx3.w)}; \
        *(uint4*)&Bb[t*PADK + 0]  = v0; \
        *(uint4*)&Bb[t*PADK + 4]  = v1; \
        *(uint4*)&Bb[t*PADK + 8]  = v2; \
        *(uint4*)&Bb[t*PADK + 12] = v3; \
    } while (0)

    float4 ax0 = *(const float4*)(xp);
    float4 ax1 = *(const float4*)(xp + 4);
    float4 bx0 = *(const float4*)(wp);
    float4 bx1 = *(const float4*)(wp + 4);
    float4 bx2 = *(const float4*)(wp + 8);
    float4 bx3 = *(const float4*)(wp + 12);
    GSTORE(0);
    __syncthreads();

    for (int kt = 0; kt < NKT; kt++) {
        const int cur = kt & 1;
        const uint32_t aoff = (uint32_t)cur * (uint32_t)A_BUF_BYTES;
        const uint32_t boff = (uint32_t)cur * (uint32_t)B_BUF_BYTES;

        if (kt + 1 < NKT) {
            const int off = (kt + 1) * 16;
            ax0 = *(const float4*)(xp + off);
            ax1 = *(const float4*)(xp + off + 4);
            bx0 = *(const float4*)(wp + off);
            bx1 = *(const float4*)(wp + off + 4);
            bx2 = *(const float4*)(wp + off + 8);
            bx3 = *(const float4*)(wp + off + 12);
        }

        #pragma unroll
        for (int ks = 0; ks < 2; ks++) {
            const uint32_t koff = (uint32_t)ks * 32u;  // 8 tf32 = 32 bytes
            uint32_t a[4][4], b[4][4];
            #pragma unroll
            for (int mi = 0; mi < 4; mi++)
                ldsm_x4(a[mi][0], a[mi][1], a[mi][2], a[mi][3],
                        aA[mi] + aoff + koff);
            #pragma unroll
            for (int np = 0; np < 4; np++)
                ldsm_x4(b[np][0], b[np][1], b[np][2], b[np][3],
                        aB[np] + boff + koff);
            #pragma unroll
            for (int mi = 0; mi < 4; mi++) {
                #pragma unroll
                for (int np = 0; np < 4; np++) {
                    mma_tf32(c[mi][2*np],   a[mi][0], a[mi][1], a[mi][2], a[mi][3],
                             b[np][0], b[np][1]);
                    mma_tf32(c[mi][2*np+1], a[mi][0], a[mi][1], a[mi][2], a[mi][3],
                             b[np][2], b[np][3]);
                }
            }
        }

        if (kt + 1 < NKT) {
            GSTORE(cur ^ 1);
        }
        __syncthreads();
    }

    #pragma unroll
    for (int mi = 0; mi < 4; mi++) {
        #pragma unroll
        for (int ni = 0; ni < 8; ni++) {
            const int row = bm + warp_m + mi*16 + qd;
            const int col = bn + warp_n + ni*8 + qk*2;
            float2 v0 = {c[mi][ni][0], c[mi][ni][1]};
            float2 v1 = {c[mi][ni][2], c[mi][ni][3]};
            *(float2*)(Y + (size_t)row * DM + col)       = v0;
            *(float2*)(Y + (size_t)(row + 8) * DM + col) = v1;
        }
    }
    #undef GSTORE
}

// ---------------------------------------------------------------------------
// Fused RMSNorm + RoPE on q and k. One block per (b*S+s, h), 128 threads.
// ---------------------------------------------------------------------------
__global__ __launch_bounds__(128) void norm_rope_kernel(
    float* __restrict__ q, float* __restrict__ k,
    const float* __restrict__ rope,
    const float* __restrict__ wq, const float* __restrict__ wk)
{
    const int row = blockIdx.x;
    const int h   = blockIdx.y;
    const int d   = threadIdx.x;
    const int s   = row & (SSEQ - 1);

    __shared__ float sh[128];
    __shared__ float red[4];

    float fr = rope[s * HD + d];
    float cs, sn;
    sincosf(fr, &sn, &cs);

    #pragma unroll
    for (int which = 0; which < 2; which++) {
        float* base = (which ? k : q) + (size_t)row * DM + h * HD;
        const float* w = which ? wk : wq;

        float x = base[d];
        float ssum = x * x;
        #pragma unroll
        for (int o = 16; o > 0; o >>= 1)
            ssum += __shfl_xor_sync(0xffffffffu, ssum, o);
        if ((d & 31) == 0) red[d >> 5] = ssum;
        __syncthreads();
        float tot = red[0] + red[1] + red[2] + red[3];
        float xn = x * rsqrtf(tot * (1.f/128.f) + 1e-6f) * w[d];
        sh[d] = xn;
        __syncthreads();
        float rot = (d < 64) ? -sh[d + 64] : sh[d - 64];
        base[d] = xn * cs + rot * sn;
        __syncthreads();
    }
}

// ---------------------------------------------------------------------------
// Flash attention with tf32 legacy mma (unchanged).
// ---------------------------------------------------------------------------
#define APQ 136
#define APS 68
#define ATT_SMEM ((64*APQ*2 + 64*APS + 64) * 4)

__global__ __launch_bounds__(256) void attn_kernel(
    const float* __restrict__ Q, const float* __restrict__ K,
    const float* __restrict__ V, float* __restrict__ O)
{
    extern __shared__ float smbuf[];
    uint32_t* Qs  = (uint32_t*)smbuf;
    uint32_t* KVs = Qs + 64 * APQ;
    float*    Ss  = (float*)(KVs + 64 * APQ);
    float* sAlpha = Ss + 64 * APS;

    const int t    = threadIdx.x;
    const int lane = t & 31;
    const int w    = t >> 5;
    const int qd   = lane >> 2;
    const int qk   = lane & 3;
    const int wm   = (w >> 1) * 16;
    const int wn_s = (w & 1) * 32;
    const int wn_v = (w & 1) * 64;
    const int g    = t >> 2;
    const int q4   = t & 3;

    const int qt = blockIdx.x;
    const int bh = blockIdx.y;
    const int b  = bh / NH;
    const int h  = bh % NH;
    const size_t base = (size_t)b * SSEQ * DM + (size_t)h * HD;
    const float* qb = Q + base;
    const float* kb = K + base;
    const float* vb = V + base;
    const int q0 = qt * 64;

    #pragma unroll
    for (int it = 0; it < 8; it++) {
        const int row = w + it * 8;
        float4 v4 = *(const float4*)(qb + (size_t)(q0 + row) * DM + lane * 4);
        uint4 u;
        u.x = f2tf32(v4.x); u.y = f2tf32(v4.y);
        u.z = f2tf32(v4.z); u.w = f2tf32(v4.w);
        *(uint4*)&Qs[row * APQ + lane * 4] = u;
    }

    float o[8][4];
    #pragma unroll
    for (int ni = 0; ni < 8; ni++)
        #pragma unroll
        for (int j = 0; j < 4; j++) o[ni][j] = 0.f;

    float m_r = -1e30f, l_r = 0.f;
    const float scale = 0.08838834764831845f;

    for (int kt = 0; kt < 16; kt++) {
        const int k0s = kt * 64;
        __syncthreads();

        #pragma unroll
        for (int it = 0; it < 8; it++) {
            const int row = w + it * 8;
            float4 v4 = *(const float4*)(kb + (size_t)(k0s + row) * DM + lane * 4);
            uint4 u;
            u.x = f2tf32(v4.x); u.y = f2tf32(v4.y);
            u.z = f2tf32(v4.z); u.w = f2tf32(v4.w);
            *(uint4*)&KVs[row * APQ + lane * 4] = u;
        }
        __syncthreads();

        float cs_[4][4];
        #pragma unroll
        for (int ni = 0; ni < 4; ni++)
            #pragma unroll
            for (int j = 0; j < 4; j++) cs_[ni][j] = 0.f;

        #pragma unroll
        for (int ks = 0; ks < 16; ks++) {
            const int k0 = ks * 8 + qk;
            uint32_t a0 = Qs[(wm + qd)     * APQ + k0];
            uint32_t a1 = Qs[(wm + qd + 8) * APQ + k0];
            uint32_t a2 = Qs[(wm + qd)     * APQ + k0 + 4];
            uint32_t a3 = Qs[(wm + qd + 8) * APQ + k0 + 4];
            #pragma unroll
            for (int ni = 0; ni < 4; ni++) {
                const int cn = wn_s + ni * 8 + qd;
                uint32_t b0 = KVs[cn * APQ + k0];
                uint32_t b1 = KVs[cn * APQ + k0 + 4];
                mma_tf32(cs_[ni], a0, a1, a2, a3, b0, b1);
            }
        }
        #pragma unroll
        for (int ni = 0; ni < 4; ni++) {
            const int col = wn_s + ni * 8 + 2 * qk;
            float2 s0 = {cs_[ni][0] * scale, cs_[ni][1] * scale};
            float2 s1 = {cs_[ni][2] * scale, cs_[ni][3] * scale};
            *(float2*)&Ss[(wm + qd)     * APS + col] = s0;
            *(float2*)&Ss[(wm + qd + 8) * APS + col] = s1;
        }
        __syncthreads();

        #pragma unroll
        for (int it = 0; it < 8; it++) {
            const int row = w + it * 8;
            float4 v4 = *(const float4*)(vb + (size_t)(k0s + row) * DM + lane * 4);
            uint4 u;
            u.x = f2tf32(v4.x); u.y = f2tf32(v4.y);
            u.z = f2tf32(v4.z); u.w = f2tf32(v4.w);
            *(uint4*)&KVs[row * APQ + lane * 4] = u;
        }

        {
            float tmax = -1e30f;
            #pragma unroll
            for (int kk = q4; kk < 64; kk += 4)
                tmax = fmaxf(tmax, Ss[g * APS + kk]);
            tmax = fmaxf(tmax, __shfl_xor_sync(0xffffffffu, tmax, 1));
            tmax = fmaxf(tmax, __shfl_xor_sync(0xffffffffu, tmax, 2));
            float mnew  = fmaxf(m_r, tmax);
            float alpha = __expf(m_r - mnew);
            float psum  = 0.f;
            #pragma unroll
            for (int kk = q4; kk < 64; kk += 4) {
                float p = __expf(Ss[g * APS + kk] - mnew);
                Ss[g * APS + kk] = p;
                psum += p;
            }
            psum += __shfl_xor_sync(0xffffffffu, psum, 1);
            psum += __shfl_xor_sync(0xffffffffu, psum, 2);
            l_r = l_r * alpha + psum;
            m_r = mnew;
            if (q4 == 0) sAlpha[g] = alpha;
        }
        __syncthreads();

        {
            const float al0 = sAlpha[wm + qd];
            const float al1 = sAlpha[wm + qd + 8];
            #pragma unroll
            for (int ni = 0; ni < 8; ni++) {
                o[ni][0] *= al0; o[ni][1] *= al0;
                o[ni][2] *= al1; o[ni][3] *= al1;
            }
        }

        #pragma unroll
        for (int ks = 0; ks < 8; ks++) {
            const int k0 = ks * 8 + qk;
            uint32_t a0 = f2tf32(Ss[(wm + qd)     * APS + k0]);
            uint32_t a1 = f2tf32(Ss[(wm + qd + 8) * APS + k0]);
            uint32_t a2 = f2tf32(Ss[(wm + qd)     * APS + k0 + 4]);
            uint32_t a3 = f2tf32(Ss[(wm + qd + 8) * APS + k0 + 4]);
            #pragma unroll
            for (int ni = 0; ni < 8; ni++) {
                const int cn = wn_v + ni * 8 + qd;
                uint32_t b0 = KVs[k0 * APQ + cn];
                uint32_t b1 = KVs[(k0 + 4) * APQ + cn];
                mma_tf32(o[ni], a0, a1, a2, a3, b0, b1);
            }
        }
    }

    if (q4 == 0) sAlpha[g] = 1.f / l_r;
    __syncthreads();
    const float li0 = sAlpha[wm + qd];
    const float li1 = sAlpha[wm + qd + 8];
    #pragma unroll
    for (int ni = 0; ni < 8; ni++) {
        const int col = wn_v + ni * 8 + 2 * qk;
        float2 v0 = {o[ni][0] * li0, o[ni][1] * li0};
        float2 v1 = {o[ni][2] * li1, o[ni][3] * li1};
        *(float2*)(O + base + (size_t)(q0 + wm + qd)     * DM + col) = v0;
        *(float2*)(O + base + (size_t)(q0 + wm + qd + 8) * DM + col) = v1;
    }
}

// ---------------------------------------------------------------------------
extern "C" void kernel_launch(void* const* d_in, const int* in_sizes, int n_in,
                              void* d_out, int out_size)
{
    const float* hidden = (const float*)d_in[0];
    const float* rope   = (const float*)d_in[1];
    const float* Wq     = (const float*)d_in[2];
    const float* Wk     = (const float*)d_in[3];
    const float* Wv     = (const float*)d_in[4];
    const float* Wo     = (const float*)d_in[5];
    const float* nqw    = (const float*)d_in[6];
    const float* nkw    = (const float*)d_in[7];
    float* out = (float*)d_out;

    float *q, *k, *v, *ao;
    cudaGetSymbolAddress((void**)&q,  g_q);
    cudaGetSymbolAddress((void**)&k,  g_k);
    cudaGetSymbolAddress((void**)&v,  g_v);
    cudaGetSymbolAddress((void**)&ao, g_ao);

    cudaFuncSetAttribute(tf32_gemm_kernel, cudaFuncAttributeMaxDynamicSharedMemorySize, GEMM_SMEM);
    cudaFuncSetAttribute(attn_kernel, cudaFuncAttributeMaxDynamicSharedMemorySize, ATT_SMEM);

    // Fused QKV projection: 3 weights x 12 n-tiles x 16 m-tiles
    tf32_gemm_kernel<<<dim3(36, 16), 256, GEMM_SMEM>>>(hidden, Wq, Wk, Wv, q, k, v, 12);

    norm_rope_kernel<<<dim3(MROWS, NH), 128>>>(q, k, rope, nqw, nkw);

    attn_kernel<<<dim3(SSEQ/64, BB*NH), 256, ATT_SMEM>>>(q, k, v, ao);

    // Output projection
    tf32_gemm_kernel<<<dim3(12, 16), 256, GEMM_SMEM>>>(ao, Wo, Wo, Wo, out, out, out, 12);
}

// round 7
// speedup vs baseline: 1.8272x; 1.8272x over previous
#include <cuda_runtime.h>
#include <cuda_fp16.h>
#include <math.h>
#include <stdint.h>

#define DM 3072
#define BB 2
#define SSEQ 1024
#define NH 24
#define HD 128
#define MROWS (BB*SSEQ)   // 2048

// Scratch (device globals: no allocations allowed)
__device__ float  g_q[MROWS*DM];
__device__ float  g_k[MROWS*DM];
__device__ float  g_v[MROWS*DM];
__device__ __half g_xh[MROWS*DM];
__device__ __half g_aoh[MROWS*DM];
__device__ __half g_wqh[DM*DM];
__device__ __half g_wkh[DM*DM];
__device__ __half g_wvh[DM*DM];
__device__ __half g_woh[DM*DM];

__device__ __forceinline__ uint32_t smem_u32(const void* p) {
    uint32_t a;
    asm("{ .reg .u64 t; cvta.to.shared.u64 t, %1; cvt.u32.u64 %0, t; }"
        : "=r"(a) : "l"(p));
    return a;
}

__device__ __forceinline__ uint32_t f2tf32(float x) {
    uint32_t r;
    asm("cvt.rna.tf32.f32 %0, %1;" : "=r"(r) : "f"(x));
    return r;
}

__device__ __forceinline__ void mma_tf32(float c[4],
    uint32_t a0, uint32_t a1, uint32_t a2, uint32_t a3,
    uint32_t b0, uint32_t b1)
{
    asm volatile(
        "mma.sync.aligned.m16n8k8.row.col.f32.tf32.tf32.f32 "
        "{%0,%1,%2,%3}, {%4,%5,%6,%7}, {%8,%9}, {%0,%1,%2,%3};"
        : "+f"(c[0]), "+f"(c[1]), "+f"(c[2]), "+f"(c[3])
        : "r"(a0), "r"(a1), "r"(a2), "r"(a3), "r"(b0), "r"(b1));
}

__device__ __forceinline__ void mma_f16(float c[4],
    uint32_t a0, uint32_t a1, uint32_t a2, uint32_t a3,
    uint32_t b0, uint32_t b1)
{
    asm volatile(
        "mma.sync.aligned.m16n8k16.row.col.f32.f16.f16.f32 "
        "{%0,%1,%2,%3}, {%4,%5,%6,%7}, {%8,%9}, {%0,%1,%2,%3};"
        : "+f"(c[0]), "+f"(c[1]), "+f"(c[2]), "+f"(c[3])
        : "r"(a0), "r"(a1), "r"(a2), "r"(a3), "r"(b0), "r"(b1));
}

__device__ __forceinline__ void ldsm_x4(
    uint32_t& r0, uint32_t& r1, uint32_t& r2, uint32_t& r3, uint32_t addr)
{
    asm volatile("ldmatrix.sync.aligned.m8n8.x4.shared.b16 {%0,%1,%2,%3}, [%4];"
        : "=r"(r0), "=r"(r1), "=r"(r2), "=r"(r3) : "r"(addr));
}

// ---------------------------------------------------------------------------
// fp32 -> fp16 conversion (grid-stride over float4s)
// ---------------------------------------------------------------------------
__global__ __launch_bounds__(256) void cvt_f32_f16(
    const float* __restrict__ src, __half* __restrict__ dst, int n4)
{
    int i = blockIdx.x * blockDim.x + threadIdx.x;
    if (i < n4) {
        float4 v = ((const float4*)src)[i];
        __half2 h0 = __floats2half2_rn(v.x, v.y);
        __half2 h1 = __floats2half2_rn(v.z, v.w);
        uint2 o;
        o.x = *(uint32_t*)&h0;
        o.y = *(uint32_t*)&h1;
        ((uint2*)dst)[i] = o;
    }
}

// ---------------------------------------------------------------------------
// fp16 GEMM: Y[m,n] = sum_k X[m,k] * W[n,k]   (fp16 operands, fp32 accum/out)
// CTA tile 128m x 128n x 32k, 8 warps (4m x 2n), warp tile 32x64.
// Double-buffered smem, 80B row stride (40 halves). Fused over <=3 weights.
// ---------------------------------------------------------------------------
#define PADH 40                     // halves per smem row (32 data + 8 pad)
#define ROWW (PADH/2)               // words per row = 20
#define BUFW (128 * ROWW)           // words per buffer = 2560
#define BUFB (BUFW * 4)             // bytes per buffer = 10240

__global__ __launch_bounds__(256, 2) void f16_gemm_kernel(
    const __half* __restrict__ X,
    const __half* __restrict__ Wa, const __half* __restrict__ Wb, const __half* __restrict__ Wc,
    float* __restrict__ Ya, float* __restrict__ Yb, float* __restrict__ Yc)
{
    __shared__ uint32_t As[2][BUFW];
    __shared__ uint32_t Bs[2][BUFW];

    const int t    = threadIdx.x;
    const int lane = t & 31;
    const int w    = t >> 5;
    const int warp_m = (w >> 1) * 32;
    const int warp_n = (w & 1) * 64;
    const int bx   = blockIdx.x;
    const int wsel = bx / 24;
    const __half* W = (wsel == 0) ? Wa : ((wsel == 1) ? Wb : Wc);
    float*        Y = (wsel == 0) ? Ya : ((wsel == 1) ? Yb : Yc);
    const int bm = blockIdx.y * 128;
    const int bn = (bx - wsel * 24) * 128;

    // Global loads: thread -> row t>>1, k-halves (t&1)*16 .. +15 (two uint4)
    const int arow = t >> 1;
    const int kh16 = (t & 1) * 16;
    const __half* xp = X + (size_t)(bm + arow) * DM + kh16;
    const __half* wp = W + (size_t)(bn + arow) * DM + kh16;
    const int swo = arow * ROWW + kh16 / 2;   // smem word offset (kh16/2 in {0,8})

    const uint32_t sAbase = smem_u32(&As[0][0]);
    const uint32_t sBbase = smem_u32(&Bs[0][0]);

    // ldmatrix per-lane addresses (buffer 0, kstep 0), byte units, row stride 80B
    const int l7 = lane & 7;
    // A: matrices m0..m3 = (rows 0-7,k0-7)(rows 8-15,k0-7)(rows 0-7,k8-15)(rows 8-15,k8-15)
    const int aArow = warp_m + ((lane >> 3) & 1) * 8 + l7;
    const int aAkh  = (lane >> 4) * 8;
    uint32_t aA[2];
    #pragma unroll
    for (int mi = 0; mi < 2; mi++)
        aA[mi] = sAbase + (uint32_t)(aArow + mi * 16) * 80u + (uint32_t)aAkh * 2u;
    // B: matrices m0..m3 = (n 0-7,k0-7)(n 0-7,k8-15)(n 8-15,k0-7)(n 8-15,k8-15)
    const int aBn  = warp_n + (lane >> 4) * 8 + l7;
    const int aBkh = ((lane >> 3) & 1) * 8;
    uint32_t aB[4];
    #pragma unroll
    for (int np = 0; np < 4; np++)
        aB[np] = sBbase + (uint32_t)(aBn + np * 16) * 80u + (uint32_t)aBkh * 2u;

    float c[2][8][4];
    #pragma unroll
    for (int mi = 0; mi < 2; mi++)
        #pragma unroll
        for (int ni = 0; ni < 8; ni++)
            #pragma unroll
            for (int j = 0; j < 4; j++) c[mi][ni][j] = 0.f;

    const int qd = lane >> 2;
    const int qk = lane & 3;
    const int NKT = DM / 32;   // 96

    #define GSTORE(buf) do { \
        *(uint4*)&As[buf][swo]     = ax0; \
        *(uint4*)&As[buf][swo + 4] = ax1; \
        *(uint4*)&Bs[buf][swo]     = bx0; \
        *(uint4*)&Bs[buf][swo + 4] = bx1; \
    } while (0)

    uint4 ax0 = *(const uint4*)(xp);
    uint4 ax1 = *(const uint4*)(xp + 8);
    uint4 bx0 = *(const uint4*)(wp);
    uint4 bx1 = *(const uint4*)(wp + 8);
    GSTORE(0);
    __syncthreads();

    for (int kt = 0; kt < NKT; kt++) {
        const int cur = kt & 1;
        const uint32_t boff = (uint32_t)cur * (uint32_t)BUFB;

        if (kt + 1 < NKT) {
            const int off = (kt + 1) * 32;
            ax0 = *(const uint4*)(xp + off);
            ax1 = *(const uint4*)(xp + off + 8);
            bx0 = *(const uint4*)(wp + off);
            bx1 = *(const uint4*)(wp + off + 8);
        }

        #pragma unroll
        for (int ks = 0; ks < 2; ks++) {
            const uint32_t koff = boff + (uint32_t)ks * 32u;  // 16 halves = 32 bytes
            uint32_t a[2][4];
            ldsm_x4(a[0][0], a[0][1], a[0][2], a[0][3], aA[0] + koff);
            ldsm_x4(a[1][0], a[1][1], a[1][2], a[1][3], aA[1] + koff);
            #pragma unroll
            for (int np = 0; np < 4; np++) {
                uint32_t b0, b1, b2, b3;
                ldsm_x4(b0, b1, b2, b3, aB[np] + koff);
                mma_f16(c[0][2*np],   a[0][0], a[0][1], a[0][2], a[0][3], b0, b1);
                mma_f16(c[1][2*np],   a[1][0], a[1][1], a[1][2], a[1][3], b0, b1);
                mma_f16(c[0][2*np+1], a[0][0], a[0][1], a[0][2], a[0][3], b2, b3);
                mma_f16(c[1][2*np+1], a[1][0], a[1][1], a[1][2], a[1][3], b2, b3);
            }
        }

        if (kt + 1 < NKT) {
            GSTORE(cur ^ 1);
        }
        __syncthreads();
    }
    #undef GSTORE

    #pragma unroll
    for (int mi = 0; mi < 2; mi++) {
        #pragma unroll
        for (int ni = 0; ni < 8; ni++) {
            const int row = bm + warp_m + mi*16 + qd;
            const int col = bn + warp_n + ni*8 + qk*2;
            float2 v0 = {c[mi][ni][0], c[mi][ni][1]};
            float2 v1 = {c[mi][ni][2], c[mi][ni][3]};
            *(float2*)(Y + (size_t)row * DM + col)       = v0;
            *(float2*)(Y + (size_t)(row + 8) * DM + col) = v1;
        }
    }
}

// ---------------------------------------------------------------------------
// Fused RMSNorm + RoPE on q and k. One block per (b*S+s, h), 128 threads.
// ---------------------------------------------------------------------------
__global__ __launch_bounds__(128) void norm_rope_kernel(
    float* __restrict__ q, float* __restrict__ k,
    const float* __restrict__ rope,
    const float* __restrict__ wq, const float* __restrict__ wk)
{
    const int row = blockIdx.x;
    const int h   = blockIdx.y;
    const int d   = threadIdx.x;
    const int s   = row & (SSEQ - 1);

    __shared__ float sh[128];
    __shared__ float red[4];

    float fr = rope[s * HD + d];
    float cs, sn;
    sincosf(fr, &sn, &cs);

    #pragma unroll
    for (int which = 0; which < 2; which++) {
        float* base = (which ? k : q) + (size_t)row * DM + h * HD;
        const float* w = which ? wk : wq;

        float x = base[d];
        float ssum = x * x;
        #pragma unroll
        for (int o = 16; o > 0; o >>= 1)
            ssum += __shfl_xor_sync(0xffffffffu, ssum, o);
        if ((d & 31) == 0) red[d >> 5] = ssum;
        __syncthreads();
        float tot = red[0] + red[1] + red[2] + red[3];
        float xn = x * rsqrtf(tot * (1.f/128.f) + 1e-6f) * w[d];
        sh[d] = xn;
        __syncthreads();
        float rot = (d < 64) ? -sh[d + 64] : sh[d - 64];
        base[d] = xn * cs + rot * sn;
        __syncthreads();
    }
}

// ---------------------------------------------------------------------------
// Flash attention with tf32 legacy mma (R5 version; epilogue writes fp16).
// ---------------------------------------------------------------------------
#define APQ 136
#define APS 68
#define ATT_SMEM ((64*APQ*2 + 64*APS + 64) * 4)

__global__ __launch_bounds__(256) void attn_kernel(
    const float* __restrict__ Q, const float* __restrict__ K,
    const float* __restrict__ V, __half* __restrict__ O)
{
    extern __shared__ float smbuf[];
    uint32_t* Qs  = (uint32_t*)smbuf;
    uint32_t* KVs = Qs + 64 * APQ;
    float*    Ss  = (float*)(KVs + 64 * APQ);
    float* sAlpha = Ss + 64 * APS;

    const int t    = threadIdx.x;
    const int lane = t & 31;
    const int w    = t >> 5;
    const int qd   = lane >> 2;
    const int qk   = lane & 3;
    const int wm   = (w >> 1) * 16;
    const int wn_s = (w & 1) * 32;
    const int wn_v = (w & 1) * 64;
    const int g    = t >> 2;
    const int q4   = t & 3;

    const int qt = blockIdx.x;
    const int bh = blockIdx.y;
    const int b  = bh / NH;
    const int h  = bh % NH;
    const size_t base = (size_t)b * SSEQ * DM + (size_t)h * HD;
    const float* qb = Q + base;
    const float* kb = K + base;
    const float* vb = V + base;
    const int q0 = qt * 64;

    #pragma unroll
    for (int it = 0; it < 8; it++) {
        const int row = w + it * 8;
        float4 v4 = *(const float4*)(qb + (size_t)(q0 + row) * DM + lane * 4);
        uint4 u;
        u.x = f2tf32(v4.x); u.y = f2tf32(v4.y);
        u.z = f2tf32(v4.z); u.w = f2tf32(v4.w);
        *(uint4*)&Qs[row * APQ + lane * 4] = u;
    }

    float o[8][4];
    #pragma unroll
    for (int ni = 0; ni < 8; ni++)
        #pragma unroll
        for (int j = 0; j < 4; j++) o[ni][j] = 0.f;

    float m_r = -1e30f, l_r = 0.f;
    const float scale = 0.08838834764831845f;

    for (int kt = 0; kt < 16; kt++) {
        const int k0s = kt * 64;
        __syncthreads();

        #pragma unroll
        for (int it = 0; it < 8; it++) {
            const int row = w + it * 8;
            float4 v4 = *(const float4*)(kb + (size_t)(k0s + row) * DM + lane * 4);
            uint4 u;
            u.x = f2tf32(v4.x); u.y = f2tf32(v4.y);
            u.z = f2tf32(v4.z); u.w = f2tf32(v4.w);
            *(uint4*)&KVs[row * APQ + lane * 4] = u;
        }
        __syncthreads();

        float cs_[4][4];
        #pragma unroll
        for (int ni = 0; ni < 4; ni++)
            #pragma unroll
            for (int j = 0; j < 4; j++) cs_[ni][j] = 0.f;

        #pragma unroll
        for (int ks = 0; ks < 16; ks++) {
            const int k0 = ks * 8 + qk;
            uint32_t a0 = Qs[(wm + qd)     * APQ + k0];
            uint32_t a1 = Qs[(wm + qd + 8) * APQ + k0];
            uint32_t a2 = Qs[(wm + qd)     * APQ + k0 + 4];
            uint32_t a3 = Qs[(wm + qd + 8) * APQ + k0 + 4];
            #pragma unroll
            for (int ni = 0; ni < 4; ni++) {
                const int cn = wn_s + ni * 8 + qd;
                uint32_t b0 = KVs[cn * APQ + k0];
                uint32_t b1 = KVs[cn * APQ + k0 + 4];
                mma_tf32(cs_[ni], a0, a1, a2, a3, b0, b1);
            }
        }
        #pragma unroll
        for (int ni = 0; ni < 4; ni++) {
            const int col = wn_s + ni * 8 + 2 * qk;
            float2 s0 = {cs_[ni][0] * scale, cs_[ni][1] * scale};
            float2 s1 = {cs_[ni][2] * scale, cs_[ni][3] * scale};
            *(float2*)&Ss[(wm + qd)     * APS + col] = s0;
            *(float2*)&Ss[(wm + qd + 8) * APS + col] = s1;
        }
        __syncthreads();

        #pragma unroll
        for (int it = 0; it < 8; it++) {
            const int row = w + it * 8;
            float4 v4 = *(const float4*)(vb + (size_t)(k0s + row) * DM + lane * 4);
            uint4 u;
            u.x = f2tf32(v4.x); u.y = f2tf32(v4.y);
            u.z = f2tf32(v4.z); u.w = f2tf32(v4.w);
            *(uint4*)&KVs[row * APQ + lane * 4] = u;
        }

        {
            float tmax = -1e30f;
            #pragma unroll
            for (int kk = q4; kk < 64; kk += 4)
                tmax = fmaxf(tmax, Ss[g * APS + kk]);
            tmax = fmaxf(tmax, __shfl_xor_sync(0xffffffffu, tmax, 1));
            tmax = fmaxf(tmax, __shfl_xor_sync(0xffffffffu, tmax, 2));
            float mnew  = fmaxf(m_r, tmax);
            float alpha = __expf(m_r - mnew);
            float psum  = 0.f;
            #pragma unroll
            for (int kk = q4; kk < 64; kk += 4) {
                float p = __expf(Ss[g * APS + kk] - mnew);
                Ss[g * APS + kk] = p;
                psum += p;
            }
            psum += __shfl_xor_sync(0xffffffffu, psum, 1);
            psum += __shfl_xor_sync(0xffffffffu, psum, 2);
            l_r = l_r * alpha + psum;
            m_r = mnew;
            if (q4 == 0) sAlpha[g] = alpha;
        }
        __syncthreads();

        {
            const float al0 = sAlpha[wm + qd];
            const float al1 = sAlpha[wm + qd + 8];
            #pragma unroll
            for (int ni = 0; ni < 8; ni++) {
                o[ni][0] *= al0; o[ni][1] *= al0;
                o[ni][2] *= al1; o[ni][3] *= al1;
            }
        }

        #pragma unroll
        for (int ks = 0; ks < 8; ks++) {
            const int k0 = ks * 8 + qk;
            uint32_t a0 = f2tf32(Ss[(wm + qd)     * APS + k0]);
            uint32_t a1 = f2tf32(Ss[(wm + qd + 8) * APS + k0]);
            uint32_t a2 = f2tf32(Ss[(wm + qd)     * APS + k0 + 4]);
            uint32_t a3 = f2tf32(Ss[(wm + qd + 8) * APS + k0 + 4]);
            #pragma unroll
            for (int ni = 0; ni < 8; ni++) {
                const int cn = wn_v + ni * 8 + qd;
                uint32_t b0 = KVs[k0 * APQ + cn];
                uint32_t b1 = KVs[(k0 + 4) * APQ + cn];
                mma_tf32(o[ni], a0, a1, a2, a3, b0, b1);
            }
        }
    }

    if (q4 == 0) sAlpha[g] = 1.f / l_r;
    __syncthreads();
    const float li0 = sAlpha[wm + qd];
    const float li1 = sAlpha[wm + qd + 8];
    #pragma unroll
    for (int ni = 0; ni < 8; ni++) {
        const int col = wn_v + ni * 8 + 2 * qk;
        __half2 h0 = __floats2half2_rn(o[ni][0] * li0, o[ni][1] * li0);
        __half2 h1 = __floats2half2_rn(o[ni][2] * li1, o[ni][3] * li1);
        *(__half2*)(O + base + (size_t)(q0 + wm + qd)     * DM + col) = h0;
        *(__half2*)(O + base + (size_t)(q0 + wm + qd + 8) * DM + col) = h1;
    }
}

// ---------------------------------------------------------------------------
extern "C" void kernel_launch(void* const* d_in, const int* in_sizes, int n_in,
                              void* d_out, int out_size)
{
    const float* hidden = (const float*)d_in[0];
    const float* rope   = (const float*)d_in[1];
    const float* Wq     = (const float*)d_in[2];
    const float* Wk     = (const float*)d_in[3];
    const float* Wv     = (const float*)d_in[4];
    const float* Wo     = (const float*)d_in[5];
    const float* nqw    = (const float*)d_in[6];
    const float* nkw    = (const float*)d_in[7];
    float* out = (float*)d_out;

    float *q, *k, *v;
    __half *xh, *aoh, *wqh, *wkh, *wvh, *woh;
    cudaGetSymbolAddress((void**)&q,   g_q);
    cudaGetSymbolAddress((void**)&k,   g_k);
    cudaGetSymbolAddress((void**)&v,   g_v);
    cudaGetSymbolAddress((void**)&xh,  g_xh);
    cudaGetSymbolAddress((void**)&aoh, g_aoh);
    cudaGetSymbolAddress((void**)&wqh, g_wqh);
    cudaGetSymbolAddress((void**)&wkh, g_wkh);
    cudaGetSymbolAddress((void**)&wvh, g_wvh);
    cudaGetSymbolAddress((void**)&woh, g_woh);

    // Pre-convert operands to fp16
    const int nX4 = MROWS * DM / 4;   // 1572864
    const int nW4 = DM * DM / 4;      // 2359296
    cvt_f32_f16<<<(nX4 + 255) / 256, 256>>>(hidden, xh, nX4);
    cvt_f32_f16<<<(nW4 + 255) / 256, 256>>>(Wq, wqh, nW4);
    cvt_f32_f16<<<(nW4 + 255) / 256, 256>>>(Wk, wkh, nW4);
    cvt_f32_f16<<<(nW4 + 255) / 256, 256>>>(Wv, wvh, nW4);
    cvt_f32_f16<<<(nW4 + 255) / 256, 256>>>(Wo, woh, nW4);

    // Fused QKV projection (fp16 tensor cores)
    f16_gemm_kernel<<<dim3(72, 16), 256>>>(xh, wqh, wkh, wvh, q, k, v);

    norm_rope_kernel<<<dim3(MROWS, NH), 128>>>(q, k, rope, nqw, nkw);

    cudaFuncSetAttribute(attn_kernel, cudaFuncAttributeMaxDynamicSharedMemorySize, ATT_SMEM);
    attn_kernel<<<dim3(SSEQ/64, BB*NH), 256, ATT_SMEM>>>(q, k, v, aoh);

    // Output projection
    f16_gemm_kernel<<<dim3(24, 16), 256>>>(aoh, woh, woh, woh, out, out, out);
}

// round 8
// speedup vs baseline: 2.1423x; 1.1724x over previous
#include <cuda_runtime.h>
#include <cuda_fp16.h>
#include <math.h>
#include <stdint.h>

#define DM 3072
#define BB 2
#define SSEQ 1024
#define NH 24
#define HD 128
#define MROWS (BB*SSEQ)   // 2048

// Scratch (device globals: no allocations allowed)
__device__ float  g_q[MROWS*DM];
__device__ float  g_k[MROWS*DM];
__device__ float  g_v[MROWS*DM];
__device__ __half g_xh[MROWS*DM];   // hidden fp16, later reused as q-hat fp16
__device__ __half g_kh[MROWS*DM];
__device__ __half g_vh[MROWS*DM];
__device__ __half g_aoh[MROWS*DM];
__device__ __half g_wqh[DM*DM];
__device__ __half g_wkh[DM*DM];
__device__ __half g_wvh[DM*DM];
__device__ __half g_woh[DM*DM];

__device__ __forceinline__ uint32_t smem_u32(const void* p) {
    uint32_t a;
    asm("{ .reg .u64 t; cvta.to.shared.u64 t, %1; cvt.u32.u64 %0, t; }"
        : "=r"(a) : "l"(p));
    return a;
}

__device__ __forceinline__ void mma_f16(float c[4],
    uint32_t a0, uint32_t a1, uint32_t a2, uint32_t a3,
    uint32_t b0, uint32_t b1)
{
    asm volatile(
        "mma.sync.aligned.m16n8k16.row.col.f32.f16.f16.f32 "
        "{%0,%1,%2,%3}, {%4,%5,%6,%7}, {%8,%9}, {%0,%1,%2,%3};"
        : "+f"(c[0]), "+f"(c[1]), "+f"(c[2]), "+f"(c[3])
        : "r"(a0), "r"(a1), "r"(a2), "r"(a3), "r"(b0), "r"(b1));
}

__device__ __forceinline__ void ldsm_x4(
    uint32_t& r0, uint32_t& r1, uint32_t& r2, uint32_t& r3, uint32_t addr)
{
    asm volatile("ldmatrix.sync.aligned.m8n8.x4.shared.b16 {%0,%1,%2,%3}, [%4];"
        : "=r"(r0), "=r"(r1), "=r"(r2), "=r"(r3) : "r"(addr));
}

__device__ __forceinline__ void ldsm_x4_t(
    uint32_t& r0, uint32_t& r1, uint32_t& r2, uint32_t& r3, uint32_t addr)
{
    asm volatile("ldmatrix.sync.aligned.m8n8.x4.trans.shared.b16 {%0,%1,%2,%3}, [%4];"
        : "=r"(r0), "=r"(r1), "=r"(r2), "=r"(r3) : "r"(addr));
}

// ---------------------------------------------------------------------------
// fp32 -> fp16 conversion (over float4s)
// ---------------------------------------------------------------------------
__global__ __launch_bounds__(256) void cvt_f32_f16(
    const float* __restrict__ src, __half* __restrict__ dst, int n4)
{
    int i = blockIdx.x * blockDim.x + threadIdx.x;
    if (i < n4) {
        float4 v = ((const float4*)src)[i];
        __half2 h0 = __floats2half2_rn(v.x, v.y);
        __half2 h1 = __floats2half2_rn(v.z, v.w);
        uint2 o;
        o.x = *(uint32_t*)&h0;
        o.y = *(uint32_t*)&h1;
        ((uint2*)dst)[i] = o;
    }
}

// ---------------------------------------------------------------------------
// fp16 GEMM (unchanged from R7): Y[m,n] = sum_k X[m,k]*W[n,k], fp32 out.
// CTA 128x128x32k, 8 warps (4m x 2n), warp 32x64, double-buffered.
// ---------------------------------------------------------------------------
#define PADH 40
#define ROWW (PADH/2)
#define BUFW (128 * ROWW)
#define BUFB (BUFW * 4)

__global__ __launch_bounds__(256, 2) void f16_gemm_kernel(
    const __half* __restrict__ X,
    const __half* __restrict__ Wa, const __half* __restrict__ Wb, const __half* __restrict__ Wc,
    float* __restrict__ Ya, float* __restrict__ Yb, float* __restrict__ Yc)
{
    __shared__ uint32_t As[2][BUFW];
    __shared__ uint32_t Bs[2][BUFW];

    const int t    = threadIdx.x;
    const int lane = t & 31;
    const int w    = t >> 5;
    const int warp_m = (w >> 1) * 32;
    const int warp_n = (w & 1) * 64;
    const int bx   = blockIdx.x;
    const int wsel = bx / 24;
    const __half* W = (wsel == 0) ? Wa : ((wsel == 1) ? Wb : Wc);
    float*        Y = (wsel == 0) ? Ya : ((wsel == 1) ? Yb : Yc);
    const int bm = blockIdx.y * 128;
    const int bn = (bx - wsel * 24) * 128;

    const int arow = t >> 1;
    const int kh16 = (t & 1) * 16;
    const __half* xp = X + (size_t)(bm + arow) * DM + kh16;
    const __half* wp = W + (size_t)(bn + arow) * DM + kh16;
    const int swo = arow * ROWW + kh16 / 2;

    const uint32_t sAbase = smem_u32(&As[0][0]);
    const uint32_t sBbase = smem_u32(&Bs[0][0]);

    const int l7 = lane & 7;
    const int aArow = warp_m + ((lane >> 3) & 1) * 8 + l7;
    const int aAkh  = (lane >> 4) * 8;
    uint32_t aA[2];
    #pragma unroll
    for (int mi = 0; mi < 2; mi++)
        aA[mi] = sAbase + (uint32_t)(aArow + mi * 16) * 80u + (uint32_t)aAkh * 2u;
    const int aBn  = warp_n + (lane >> 4) * 8 + l7;
    const int aBkh = ((lane >> 3) & 1) * 8;
    uint32_t aB[4];
    #pragma unroll
    for (int np = 0; np < 4; np++)
        aB[np] = sBbase + (uint32_t)(aBn + np * 16) * 80u + (uint32_t)aBkh * 2u;

    float c[2][8][4];
    #pragma unroll
    for (int mi = 0; mi < 2; mi++)
        #pragma unroll
        for (int ni = 0; ni < 8; ni++)
            #pragma unroll
            for (int j = 0; j < 4; j++) c[mi][ni][j] = 0.f;

    const int qd = lane >> 2;
    const int qk = lane & 3;
    const int NKT = DM / 32;

    #define GSTORE(buf) do { \
        *(uint4*)&As[buf][swo]     = ax0; \
        *(uint4*)&As[buf][swo + 4] = ax1; \
        *(uint4*)&Bs[buf][swo]     = bx0; \
        *(uint4*)&Bs[buf][swo + 4] = bx1; \
    } while (0)

    uint4 ax0 = *(const uint4*)(xp);
    uint4 ax1 = *(const uint4*)(xp + 8);
    uint4 bx0 = *(const uint4*)(wp);
    uint4 bx1 = *(const uint4*)(wp + 8);
    GSTORE(0);
    __syncthreads();

    for (int kt = 0; kt < NKT; kt++) {
        const int cur = kt & 1;
        const uint32_t boff = (uint32_t)cur * (uint32_t)BUFB;

        if (kt + 1 < NKT) {
            const int off = (kt + 1) * 32;
            ax0 = *(const uint4*)(xp + off);
            ax1 = *(const uint4*)(xp + off + 8);
            bx0 = *(const uint4*)(wp + off);
            bx1 = *(const uint4*)(wp + off + 8);
        }

        #pragma unroll
        for (int ks = 0; ks < 2; ks++) {
            const uint32_t koff = boff + (uint32_t)ks * 32u;
            uint32_t a[2][4];
            ldsm_x4(a[0][0], a[0][1], a[0][2], a[0][3], aA[0] + koff);
            ldsm_x4(a[1][0], a[1][1], a[1][2], a[1][3], aA[1] + koff);
            #pragma unroll
            for (int np = 0; np < 4; np++) {
                uint32_t b0, b1, b2, b3;
                ldsm_x4(b0, b1, b2, b3, aB[np] + koff);
                mma_f16(c[0][2*np],   a[0][0], a[0][1], a[0][2], a[0][3], b0, b1);
                mma_f16(c[1][2*np],   a[1][0], a[1][1], a[1][2], a[1][3], b0, b1);
                mma_f16(c[0][2*np+1], a[0][0], a[0][1], a[0][2], a[0][3], b2, b3);
                mma_f16(c[1][2*np+1], a[1][0], a[1][1], a[1][2], a[1][3], b2, b3);
            }
        }

        if (kt + 1 < NKT) {
            GSTORE(cur ^ 1);
        }
        __syncthreads();
    }
    #undef GSTORE

    #pragma unroll
    for (int mi = 0; mi < 2; mi++) {
        #pragma unroll
        for (int ni = 0; ni < 8; ni++) {
            const int row = bm + warp_m + mi*16 + qd;
            const int col = bn + warp_n + ni*8 + qk*2;
            float2 v0 = {c[mi][ni][0], c[mi][ni][1]};
            float2 v1 = {c[mi][ni][2], c[mi][ni][3]};
            *(float2*)(Y + (size_t)row * DM + col)       = v0;
            *(float2*)(Y + (size_t)(row + 8) * DM + col) = v1;
        }
    }
}

// ---------------------------------------------------------------------------
// Fused RMSNorm + RoPE; emits fp16 q-hat/k-hat, converts v to fp16.
// One block per (b*S+s, h), 128 threads.
// ---------------------------------------------------------------------------
__global__ __launch_bounds__(128) void norm_rope_kernel(
    const float* __restrict__ q, const float* __restrict__ k,
    const float* __restrict__ v,
    __half* __restrict__ qh, __half* __restrict__ kh, __half* __restrict__ vh,
    const float* __restrict__ rope,
    const float* __restrict__ wq, const float* __restrict__ wk)
{
    const int row = blockIdx.x;
    const int h   = blockIdx.y;
    const int d   = threadIdx.x;
    const int s   = row & (SSEQ - 1);
    const size_t idx = (size_t)row * DM + h * HD + d;

    __shared__ float sh[128];
    __shared__ float red[4];

    float fr = rope[s * HD + d];
    float cs, sn;
    sincosf(fr, &sn, &cs);

    vh[idx] = __float2half_rn(v[idx]);

    #pragma unroll
    for (int which = 0; which < 2; which++) {
        const float* src = which ? k : q;
        __half* dst      = which ? kh : qh;
        const float* w   = which ? wk : wq;

        float x = src[idx];
        float ssum = x * x;
        #pragma unroll
        for (int o = 16; o > 0; o >>= 1)
            ssum += __shfl_xor_sync(0xffffffffu, ssum, o);
        if ((d & 31) == 0) red[d >> 5] = ssum;
        __syncthreads();
        float tot = red[0] + red[1] + red[2] + red[3];
        float xn = x * rsqrtf(tot * (1.f/128.f) + 1e-6f) * w[d];
        sh[d] = xn;
        __syncthreads();
        float rot = (d < 64) ? -sh[d + 64] : sh[d - 64];
        dst[idx] = __float2half_rn(xn * cs + rot * sn);
        __syncthreads();
    }
}

// ---------------------------------------------------------------------------
// fp16 flash attention. 256 threads (8 warps), 64 q-rows, 16 k-tiles of 64.
// Scores warp tile 16x32 (4m x 2n), PV warp tile 16x64.
// Smem: Qh[64][136]h, KV[64][136]h (K then V), Ss[64][68]f, Ph[64][72]h.
// ---------------------------------------------------------------------------
#define QSTH 136
#define QSTB (QSTH*2)     // 272 bytes/row
#define SSTW 68
#define PSTH 72
#define PSTB (PSTH*2)     // 144 bytes/row
#define ATT_SMEM (64*QSTB*2 + 64*SSTW*4 + 64*PSTB + 256)

__global__ __launch_bounds__(256) void attn_kernel(
    const __half* __restrict__ Q, const __half* __restrict__ K,
    const __half* __restrict__ V, __half* __restrict__ O)
{
    extern __shared__ char smraw[];
    __half* Qh = (__half*)smraw;
    __half* KV = Qh + 64 * QSTH;
    float*  Ss = (float*)(KV + 64 * QSTH);
    __half* Ph = (__half*)(Ss + 64 * SSTW);
    float* sAlpha = (float*)(Ph + 64 * PSTH);

    const uint32_t sQ = smem_u32(Qh);
    const uint32_t sK = smem_u32(KV);
    const uint32_t sP = smem_u32(Ph);

    const int t    = threadIdx.x;
    const int lane = t & 31;
    const int w    = t >> 5;
    const int qd   = lane >> 2;
    const int qk   = lane & 3;
    const int wm   = (w >> 1) * 16;   // mma row base
    const int wn_s = (w & 1) * 32;    // scores col base
    const int wn_v = (w & 1) * 64;    // PV col base
    const int g    = t >> 2;          // softmax row
    const int q4   = t & 3;           // softmax lane-in-row

    const int qt = blockIdx.x;
    const int bh = blockIdx.y;
    const int b  = bh / NH;
    const int h  = bh % NH;
    const size_t base = (size_t)b * SSEQ * DM + (size_t)h * HD;
    const __half* qb = Q + base;
    const __half* kb = K + base;
    const __half* vb = V + base;
    const int q0 = qt * 64;

    // ldmatrix addresses (per-lane)
    const int l7 = lane & 7;
    const int arow = ((lane >> 3) & 1) * 8 + l7;
    const int akh  = (lane >> 4) * 8;
    const uint32_t aQ = sQ + (uint32_t)(wm + arow) * QSTB + (uint32_t)akh * 2u;
    const uint32_t aP = sP + (uint32_t)(wm + arow) * PSTB + (uint32_t)akh * 2u;
    const int bn  = (lane >> 4) * 8 + l7;
    const int bkh = ((lane >> 3) & 1) * 8;
    const uint32_t aK0 = sK + (uint32_t)(wn_s + bn) * QSTB + (uint32_t)bkh * 2u;
    const uint32_t aK1 = aK0 + 16u * QSTB;
    // V (trans): k-rows, n-cols
    const uint32_t aV = sK + (uint32_t)(((lane >> 3) & 1) * 8 + l7) * QSTB
                      + (uint32_t)(wn_v + (lane >> 4) * 8) * 2u;

    // Load Q tile: 64 rows x 128 halves = 1024 uint4
    #pragma unroll
    for (int it = 0; it < 4; it++) {
        const int f   = t + it * 256;
        const int row = f >> 4;
        const int c8  = (f & 15) * 8;
        uint4 u = *(const uint4*)(qb + (size_t)(q0 + row) * DM + c8);
        *(uint4*)(Qh + row * QSTH + c8) = u;
    }

    float o[8][4];
    #pragma unroll
    for (int ni = 0; ni < 8; ni++)
        #pragma unroll
        for (int j = 0; j < 4; j++) o[ni][j] = 0.f;

    float m_r = -1e30f, l_r = 0.f;
    const float scale = 0.08838834764831845f;

    for (int kt = 0; kt < 16; kt++) {
        const int k0s = kt * 64;
        __syncthreads();   // prior iter's KV/Ph reads complete (covers Q load on kt=0)

        // Load K tile
        #pragma unroll
        for (int it = 0; it < 4; it++) {
            const int f   = t + it * 256;
            const int row = f >> 4;
            const int c8  = (f & 15) * 8;
            uint4 u = *(const uint4*)(kb + (size_t)(k0s + row) * DM + c8);
            *(uint4*)(KV + row * QSTH + c8) = u;
        }
        __syncthreads();

        // Scores: S[64x64] = Q @ K^T
        float cs_[4][4];
        #pragma unroll
        for (int ni = 0; ni < 4; ni++)
            #pragma unroll
            for (int j = 0; j < 4; j++) cs_[ni][j] = 0.f;

        #pragma unroll
        for (int ks = 0; ks < 8; ks++) {
            const uint32_t koff = (uint32_t)ks * 32u;
            uint32_t a0, a1, a2, a3, b0, b1, b2, b3;
            ldsm_x4(a0, a1, a2, a3, aQ + koff);
            ldsm_x4(b0, b1, b2, b3, aK0 + koff);
            mma_f16(cs_[0], a0, a1, a2, a3, b0, b1);
            mma_f16(cs_[1], a0, a1, a2, a3, b2, b3);
            ldsm_x4(b0, b1, b2, b3, aK1 + koff);
            mma_f16(cs_[2], a0, a1, a2, a3, b0, b1);
            mma_f16(cs_[3], a0, a1, a2, a3, b2, b3);
        }
        #pragma unroll
        for (int ni = 0; ni < 4; ni++) {
            const int col = wn_s + ni * 8 + 2 * qk;
            float2 s0 = {cs_[ni][0] * scale, cs_[ni][1] * scale};
            float2 s1 = {cs_[ni][2] * scale, cs_[ni][3] * scale};
            *(float2*)&Ss[(wm + qd)     * SSTW + col] = s0;
            *(float2*)&Ss[(wm + qd + 8) * SSTW + col] = s1;
        }
        __syncthreads();   // scores visible; K reads done

        // Load V tile (overwrites K)
        #pragma unroll
        for (int it = 0; it < 4; it++) {
            const int f   = t + it * 256;
            const int row = f >> 4;
            const int c8  = (f & 15) * 8;
            uint4 u = *(const uint4*)(vb + (size_t)(k0s + row) * DM + c8);
            *(uint4*)(KV + row * QSTH + c8) = u;
        }

        // Online softmax: row g, lane-chunk of 16 contiguous cols
        {
            const int sb = g * SSTW + q4 * 16;
            float tmax = -1e30f;
            #pragma unroll
            for (int i = 0; i < 16; i++)
                tmax = fmaxf(tmax, Ss[sb + i]);
            tmax = fmaxf(tmax, __shfl_xor_sync(0xffffffffu, tmax, 1));
            tmax = fmaxf(tmax, __shfl_xor_sync(0xffffffffu, tmax, 2));
            float mnew  = fmaxf(m_r, tmax);
            float alpha = __expf(m_r - mnew);
            float psum  = 0.f;
            const int pb = g * PSTH + q4 * 16;
            #pragma unroll
            for (int i = 0; i < 8; i++) {
                float p0 = __expf(Ss[sb + 2*i]     - mnew);
                float p1 = __expf(Ss[sb + 2*i + 1] - mnew);
                *(__half2*)(Ph + pb + 2*i) = __floats2half2_rn(p0, p1);
                psum += p0 + p1;
            }
            psum += __shfl_xor_sync(0xffffffffu, psum, 1);
            psum += __shfl_xor_sync(0xffffffffu, psum, 2);
            l_r = l_r * alpha + psum;
            m_r = mnew;
            if (q4 == 0) sAlpha[g] = alpha;
        }
        __syncthreads();   // V, Ph, alpha visible

        // Rescale accumulators
        {
            const float al0 = sAlpha[wm + qd];
            const float al1 = sAlpha[wm + qd + 8];
            #pragma unroll
            for (int ni = 0; ni < 8; ni++) {
                o[ni][0] *= al0; o[ni][1] *= al0;
                o[ni][2] *= al1; o[ni][3] *= al1;
            }
        }

        // PV: O[64x128] += P[64x64] @ V[64x128]
        #pragma unroll
        for (int ks = 0; ks < 4; ks++) {
            uint32_t a0, a1, a2, a3;
            ldsm_x4(a0, a1, a2, a3, aP + (uint32_t)ks * 32u);
            const uint32_t vko = (uint32_t)ks * 16u * QSTB;
            #pragma unroll
            for (int np = 0; np < 4; np++) {
                uint32_t b0, b1, b2, b3;
                ldsm_x4_t(b0, b1, b2, b3, aV + vko + (uint32_t)np * 32u);
                mma_f16(o[2*np],   a0, a1, a2, a3, b0, b1);
                mma_f16(o[2*np+1], a0, a1, a2, a3, b2, b3);
            }
        }
    }

    if (q4 == 0) sAlpha[g] = 1.f / l_r;
    __syncthreads();
    const float li0 = sAlpha[wm + qd];
    const float li1 = sAlpha[wm + qd + 8];
    #pragma unroll
    for (int ni = 0; ni < 8; ni++) {
        const int col = wn_v + ni * 8 + 2 * qk;
        __half2 h0 = __floats2half2_rn(o[ni][0] * li0, o[ni][1] * li0);
        __half2 h1 = __floats2half2_rn(o[ni][2] * li1, o[ni][3] * li1);
        *(__half2*)(O + base + (size_t)(q0 + wm + qd)     * DM + col) = h0;
        *(__half2*)(O + base + (size_t)(q0 + wm + qd + 8) * DM + col) = h1;
    }
}

// ---------------------------------------------------------------------------
extern "C" void kernel_launch(void* const* d_in, const int* in_sizes, int n_in,
                              void* d_out, int out_size)
{
    const float* hidden = (const float*)d_in[0];
    const float* rope   = (const float*)d_in[1];
    const float* Wq     = (const float*)d_in[2];
    const float* Wk     = (const float*)d_in[3];
    const float* Wv     = (const float*)d_in[4];
    const float* Wo     = (const float*)d_in[5];
    const float* nqw    = (const float*)d_in[6];
    const float* nkw    = (const float*)d_in[7];
    float* out = (float*)d_out;

    float *q, *k, *v;
    __half *xh, *kh, *vh, *aoh, *wqh, *wkh, *wvh, *woh;
    cudaGetSymbolAddress((void**)&q,   g_q);
    cudaGetSymbolAddress((void**)&k,   g_k);
    cudaGetSymbolAddress((void**)&v,   g_v);
    cudaGetSymbolAddress((void**)&xh,  g_xh);
    cudaGetSymbolAddress((void**)&kh,  g_kh);
    cudaGetSymbolAddress((void**)&vh,  g_vh);
    cudaGetSymbolAddress((void**)&aoh, g_aoh);
    cudaGetSymbolAddress((void**)&wqh, g_wqh);
    cudaGetSymbolAddress((void**)&wkh, g_wkh);
    cudaGetSymbolAddress((void**)&wvh, g_wvh);
    cudaGetSymbolAddress((void**)&woh, g_woh);

    const int nX4 = MROWS * DM / 4;
    const int nW4 = DM * DM / 4;
    cvt_f32_f16<<<(nX4 + 255) / 256, 256>>>(hidden, xh, nX4);
    cvt_f32_f16<<<(nW4 + 255) / 256, 256>>>(Wq, wqh, nW4);
    cvt_f32_f16<<<(nW4 + 255) / 256, 256>>>(Wk, wkh, nW4);
    cvt_f32_f16<<<(nW4 + 255) / 256, 256>>>(Wv, wvh, nW4);
    cvt_f32_f16<<<(nW4 + 255) / 256, 256>>>(Wo, woh, nW4);

    // Fused QKV projection (fp16 in, fp32 out)
    f16_gemm_kernel<<<dim3(72, 16), 256>>>(xh, wqh, wkh, wvh, q, k, v);

    // Norm+RoPE: reads fp32 q/k/v, writes fp16 q-hat (into xh), k-hat, v
    norm_rope_kernel<<<dim3(MROWS, NH), 128>>>(q, k, v, xh, kh, vh, rope, nqw, nkw);

    cudaFuncSetAttribute(attn_kernel, cudaFuncAttributeMaxDynamicSharedMemorySize, ATT_SMEM);
    attn_kernel<<<dim3(SSEQ/64, BB*NH), 256, ATT_SMEM>>>(xh, kh, vh, aoh);

    // Output projection
    f16_gemm_kernel<<<dim3(24, 16), 256>>>(aoh, woh, woh, woh, out, out, out);
}

// round 9
// speedup vs baseline: 2.4784x; 1.1569x over previous
#include <cuda_runtime.h>
#include <cuda_fp16.h>
#include <math.h>
#include <stdint.h>

#define DM 3072
#define BB 2
#define SSEQ 1024
#define NH 24
#define HD 128
#define MROWS (BB*SSEQ)   // 2048

// Scratch (device globals: no allocations allowed)
__device__ float  g_q[MROWS*DM];
__device__ float  g_k[MROWS*DM];
__device__ __half g_xh[MROWS*DM];   // hidden fp16, later reused as q-hat fp16
__device__ __half g_kh[MROWS*DM];
__device__ __half g_vh[MROWS*DM];
__device__ __half g_aoh[MROWS*DM];
__device__ __half g_wqh[DM*DM];
__device__ __half g_wkh[DM*DM];
__device__ __half g_wvh[DM*DM];
__device__ __half g_woh[DM*DM];

__device__ __forceinline__ uint32_t smem_u32(const void* p) {
    uint32_t a;
    asm("{ .reg .u64 t; cvta.to.shared.u64 t, %1; cvt.u32.u64 %0, t; }"
        : "=r"(a) : "l"(p));
    return a;
}

__device__ __forceinline__ void mma_f16(float c[4],
    uint32_t a0, uint32_t a1, uint32_t a2, uint32_t a3,
    uint32_t b0, uint32_t b1)
{
    asm volatile(
        "mma.sync.aligned.m16n8k16.row.col.f32.f16.f16.f32 "
        "{%0,%1,%2,%3}, {%4,%5,%6,%7}, {%8,%9}, {%0,%1,%2,%3};"
        : "+f"(c[0]), "+f"(c[1]), "+f"(c[2]), "+f"(c[3])
        : "r"(a0), "r"(a1), "r"(a2), "r"(a3), "r"(b0), "r"(b1));
}

__device__ __forceinline__ void ldsm_x4(
    uint32_t& r0, uint32_t& r1, uint32_t& r2, uint32_t& r3, uint32_t addr)
{
    asm volatile("ldmatrix.sync.aligned.m8n8.x4.shared.b16 {%0,%1,%2,%3}, [%4];"
        : "=r"(r0), "=r"(r1), "=r"(r2), "=r"(r3) : "r"(addr));
}

__device__ __forceinline__ void ldsm_x4_t(
    uint32_t& r0, uint32_t& r1, uint32_t& r2, uint32_t& r3, uint32_t addr)
{
    asm volatile("ldmatrix.sync.aligned.m8n8.x4.trans.shared.b16 {%0,%1,%2,%3}, [%4];"
        : "=r"(r0), "=r"(r1), "=r"(r2), "=r"(r3) : "r"(addr));
}

__device__ __forceinline__ void cp_async16(uint32_t saddr, const void* gptr) {
    asm volatile("cp.async.cg.shared.global [%0], [%1], 16;"
        :: "r"(saddr), "l"(gptr) : "memory");
}
#define CP_COMMIT() asm volatile("cp.async.commit_group;" ::: "memory")
#define CP_WAIT2()  asm volatile("cp.async.wait_group 2;" ::: "memory")

// ---------------------------------------------------------------------------
// fp32 -> fp16 conversion (over float4s)
// ---------------------------------------------------------------------------
__global__ __launch_bounds__(256) void cvt_f32_f16(
    const float* __restrict__ src, __half* __restrict__ dst, int n4)
{
    int i = blockIdx.x * blockDim.x + threadIdx.x;
    if (i < n4) {
        float4 v = ((const float4*)src)[i];
        __half2 h0 = __floats2half2_rn(v.x, v.y);
        __half2 h1 = __floats2half2_rn(v.z, v.w);
        uint2 o;
        o.x = *(uint32_t*)&h0;
        o.y = *(uint32_t*)&h1;
        ((uint2*)dst)[i] = o;
    }
}

// ---------------------------------------------------------------------------
// fp16 GEMM, cp.async 4-stage pipeline. Y[m,n] = sum_k X[m,k]*W[n,k].
// CTA 128x128x32k, 8 warps (4m x 2n), warp 32x64.
// Outputs: wsel 0/1 -> fp32 (Ya/Yb), wsel 2 -> fp16 (Yc).
// Stage layout: A 128x40h (10240B) then B 128x40h; stage stride 20480B.
// ---------------------------------------------------------------------------
#define STAGEB 20480
#define NSTAGE 4
#define GEMM_SMEM (NSTAGE * STAGEB)   // 81920

__global__ __launch_bounds__(256, 2) void f16_gemm_kernel(
    const __half* __restrict__ X,
    const __half* __restrict__ Wa, const __half* __restrict__ Wb, const __half* __restrict__ Wc,
    float* __restrict__ Ya, float* __restrict__ Yb, __half* __restrict__ Yc)
{
    extern __shared__ char smraw[];
    const uint32_t smb = smem_u32(smraw);

    const int t    = threadIdx.x;
    const int lane = t & 31;
    const int w    = t >> 5;
    const int warp_m = (w >> 1) * 32;
    const int warp_n = (w & 1) * 64;
    const int bx   = blockIdx.x;
    const int wsel = bx / 24;
    const __half* W = (wsel == 0) ? Wa : ((wsel == 1) ? Wb : Wc);
    const int bm = blockIdx.y * 128;
    const int bn = (bx - wsel * 24) * 128;

    // cp.async mapping: thread -> row t>>1, k-halves (t&1)*16 (two 16B chunks)
    const int arow = t >> 1;
    const int kh16 = (t & 1) * 16;
    const __half* xp = X + (size_t)(bm + arow) * DM + kh16;
    const __half* wp = W + (size_t)(bn + arow) * DM + kh16;
    const uint32_t srow = (uint32_t)arow * 80u + (uint32_t)kh16 * 2u; // byte off in stage

    // ldmatrix per-lane byte offsets relative to stage base
    const int l7 = lane & 7;
    const int aArow = warp_m + ((lane >> 3) & 1) * 8 + l7;
    const int aAkh  = (lane >> 4) * 8;
    uint32_t offA[2];
    #pragma unroll
    for (int mi = 0; mi < 2; mi++)
        offA[mi] = (uint32_t)(aArow + mi * 16) * 80u + (uint32_t)aAkh * 2u;
    const int aBn  = warp_n + (lane >> 4) * 8 + l7;
    const int aBkh = ((lane >> 3) & 1) * 8;
    uint32_t offB[4];
    #pragma unroll
    for (int np = 0; np < 4; np++)
        offB[np] = 10240u + (uint32_t)(aBn + np * 16) * 80u + (uint32_t)aBkh * 2u;

    float c[2][8][4];
    #pragma unroll
    for (int mi = 0; mi < 2; mi++)
        #pragma unroll
        for (int ni = 0; ni < 8; ni++)
            #pragma unroll
            for (int j = 0; j < 4; j++) c[mi][ni][j] = 0.f;

    const int qd = lane >> 2;
    const int qk = lane & 3;
    const int NKT = DM / 32;   // 96

    #define ISSUE(kt_, buf_) do { \
        const uint32_t sa = smb + (uint32_t)(buf_) * STAGEB + srow; \
        const __half* xg = xp + (kt_) * 32; \
        const __half* wg = wp + (kt_) * 32; \
        cp_async16(sa,           xg); \
        cp_async16(sa + 16u,     xg + 8); \
        cp_async16(sa + 10240u,      wg); \
        cp_async16(sa + 10240u + 16u, wg + 8); \
    } while (0)

    // Prologue: stages 0..2
    ISSUE(0, 0); CP_COMMIT();
    ISSUE(1, 1); CP_COMMIT();
    ISSUE(2, 2); CP_COMMIT();

    int buf = 0;
    for (int kt = 0; kt < NKT; kt++) {
        CP_WAIT2();          // stage kt landed
        __syncthreads();

        const int nkt = kt + 3;
        if (nkt < NKT) {
            const int nbuf = (buf + 3) & 3;
            ISSUE(nkt, nbuf);
        }
        CP_COMMIT();

        const uint32_t st = smb + (uint32_t)buf * STAGEB;
        #pragma unroll
        for (int ks = 0; ks < 2; ks++) {
            const uint32_t koff = (uint32_t)ks * 32u;
            uint32_t a[2][4];
            ldsm_x4(a[0][0], a[0][1], a[0][2], a[0][3], st + offA[0] + koff);
            ldsm_x4(a[1][0], a[1][1], a[1][2], a[1][3], st + offA[1] + koff);
            #pragma unroll
            for (int np = 0; np < 4; np++) {
                uint32_t b0, b1, b2, b3;
                ldsm_x4(b0, b1, b2, b3, st + offB[np] + koff);
                mma_f16(c[0][2*np],   a[0][0], a[0][1], a[0][2], a[0][3], b0, b1);
                mma_f16(c[1][2*np],   a[1][0], a[1][1], a[1][2], a[1][3], b0, b1);
                mma_f16(c[0][2*np+1], a[0][0], a[0][1], a[0][2], a[0][3], b2, b3);
                mma_f16(c[1][2*np+1], a[1][0], a[1][1], a[1][2], a[1][3], b2, b3);
            }
        }
        buf = (buf + 1) & 3;
        __syncthreads();     // all warps done with stage kt before it is refilled
    }
    #undef ISSUE

    if (wsel < 2) {
        float* Y = wsel ? Yb : Ya;
        #pragma unroll
        for (int mi = 0; mi < 2; mi++) {
            #pragma unroll
            for (int ni = 0; ni < 8; ni++) {
                const int row = bm + warp_m + mi*16 + qd;
                const int col = bn + warp_n + ni*8 + qk*2;
                float2 v0 = {c[mi][ni][0], c[mi][ni][1]};
                float2 v1 = {c[mi][ni][2], c[mi][ni][3]};
                *(float2*)(Y + (size_t)row * DM + col)       = v0;
                *(float2*)(Y + (size_t)(row + 8) * DM + col) = v1;
            }
        }
    } else {
        // V output: write fp16 directly
        #pragma unroll
        for (int mi = 0; mi < 2; mi++) {
            #pragma unroll
            for (int ni = 0; ni < 8; ni++) {
                const int row = bm + warp_m + mi*16 + qd;
                const int col = bn + warp_n + ni*8 + qk*2;
                __half2 h0 = __floats2half2_rn(c[mi][ni][0], c[mi][ni][1]);
                __half2 h1 = __floats2half2_rn(c[mi][ni][2], c[mi][ni][3]);
                *(__half2*)(Yc + (size_t)row * DM + col)       = h0;
                *(__half2*)(Yc + (size_t)(row + 8) * DM + col) = h1;
            }
        }
    }
}

// ---------------------------------------------------------------------------
// Fused RMSNorm + RoPE; emits fp16 q-hat/k-hat. One block per (row, h).
// ---------------------------------------------------------------------------
__global__ __launch_bounds__(128) void norm_rope_kernel(
    const float* __restrict__ q, const float* __restrict__ k,
    __half* __restrict__ qh, __half* __restrict__ kh,
    const float* __restrict__ rope,
    const float* __restrict__ wq, const float* __restrict__ wk)
{
    const int row = blockIdx.x;
    const int h   = blockIdx.y;
    const int d   = threadIdx.x;
    const int s   = row & (SSEQ - 1);
    const size_t idx = (size_t)row * DM + h * HD + d;

    __shared__ float sh[128];
    __shared__ float red[4];

    float fr = rope[s * HD + d];
    float cs, sn;
    sincosf(fr, &sn, &cs);

    #pragma unroll
    for (int which = 0; which < 2; which++) {
        const float* src = which ? k : q;
        __half* dst      = which ? kh : qh;
        const float* w   = which ? wk : wq;

        float x = src[idx];
        float ssum = x * x;
        #pragma unroll
        for (int o = 16; o > 0; o >>= 1)
            ssum += __shfl_xor_sync(0xffffffffu, ssum, o);
        if ((d & 31) == 0) red[d >> 5] = ssum;
        __syncthreads();
        float tot = red[0] + red[1] + red[2] + red[3];
        float xn = x * rsqrtf(tot * (1.f/128.f) + 1e-6f) * w[d];
        sh[d] = xn;
        __syncthreads();
        float rot = (d < 64) ? -sh[d + 64] : sh[d - 64];
        dst[idx] = __float2half_rn(xn * cs + rot * sn);
        __syncthreads();
    }
}

// ---------------------------------------------------------------------------
// fp16 flash attention (unchanged from R8).
// ---------------------------------------------------------------------------
#define QSTH 136
#define QSTB (QSTH*2)
#define SSTW 68
#define PSTH 72
#define PSTB (PSTH*2)
#define ATT_SMEM (64*QSTB*2 + 64*SSTW*4 + 64*PSTB + 256)

__global__ __launch_bounds__(256) void attn_kernel(
    const __half* __restrict__ Q, const __half* __restrict__ K,
    const __half* __restrict__ V, __half* __restrict__ O)
{
    extern __shared__ char smraw[];
    __half* Qh = (__half*)smraw;
    __half* KV = Qh + 64 * QSTH;
    float*  Ss = (float*)(KV + 64 * QSTH);
    __half* Ph = (__half*)(Ss + 64 * SSTW);
    float* sAlpha = (float*)(Ph + 64 * PSTH);

    const uint32_t sQ = smem_u32(Qh);
    const uint32_t sK = smem_u32(KV);
    const uint32_t sP = smem_u32(Ph);

    const int t    = threadIdx.x;
    const int lane = t & 31;
    const int w    = t >> 5;
    const int qd   = lane >> 2;
    const int qk   = lane & 3;
    const int wm   = (w >> 1) * 16;
    const int wn_s = (w & 1) * 32;
    const int wn_v = (w & 1) * 64;
    const int g    = t >> 2;
    const int q4   = t & 3;

    const int qt = blockIdx.x;
    const int bh = blockIdx.y;
    const int b  = bh / NH;
    const int h  = bh % NH;
    const size_t base = (size_t)b * SSEQ * DM + (size_t)h * HD;
    const __half* qb = Q + base;
    const __half* kb = K + base;
    const __half* vb = V + base;
    const int q0 = qt * 64;

    const int l7 = lane & 7;
    const int arow = ((lane >> 3) & 1) * 8 + l7;
    const int akh  = (lane >> 4) * 8;
    const uint32_t aQ = sQ + (uint32_t)(wm + arow) * QSTB + (uint32_t)akh * 2u;
    const uint32_t aP = sP + (uint32_t)(wm + arow) * PSTB + (uint32_t)akh * 2u;
    const int bn  = (lane >> 4) * 8 + l7;
    const int bkh = ((lane >> 3) & 1) * 8;
    const uint32_t aK0 = sK + (uint32_t)(wn_s + bn) * QSTB + (uint32_t)bkh * 2u;
    const uint32_t aK1 = aK0 + 16u * QSTB;
    const uint32_t aV = sK + (uint32_t)(((lane >> 3) & 1) * 8 + l7) * QSTB
                      + (uint32_t)(wn_v + (lane >> 4) * 8) * 2u;

    #pragma unroll
    for (int it = 0; it < 4; it++) {
        const int f   = t + it * 256;
        const int row = f >> 4;
        const int c8  = (f & 15) * 8;
        uint4 u = *(const uint4*)(qb + (size_t)(q0 + row) * DM + c8);
        *(uint4*)(Qh + row * QSTH + c8) = u;
    }

    float o[8][4];
    #pragma unroll
    for (int ni = 0; ni < 8; ni++)
        #pragma unroll
        for (int j = 0; j < 4; j++) o[ni][j] = 0.f;

    float m_r = -1e30f, l_r = 0.f;
    const float scale = 0.08838834764831845f;

    for (int kt = 0; kt < 16; kt++) {
        const int k0s = kt * 64;
        __syncthreads();

        #pragma unroll
        for (int it = 0; it < 4; it++) {
            const int f   = t + it * 256;
            const int row = f >> 4;
            const int c8  = (f & 15) * 8;
            uint4 u = *(const uint4*)(kb + (size_t)(k0s + row) * DM + c8);
            *(uint4*)(KV + row * QSTH + c8) = u;
        }
        __syncthreads();

        float cs_[4][4];
        #pragma unroll
        for (int ni = 0; ni < 4; ni++)
            #pragma unroll
            for (int j = 0; j < 4; j++) cs_[ni][j] = 0.f;

        #pragma unroll
        for (int ks = 0; ks < 8; ks++) {
            const uint32_t koff = (uint32_t)ks * 32u;
            uint32_t a0, a1, a2, a3, b0, b1, b2, b3;
            ldsm_x4(a0, a1, a2, a3, aQ + koff);
            ldsm_x4(b0, b1, b2, b3, aK0 + koff);
            mma_f16(cs_[0], a0, a1, a2, a3, b0, b1);
            mma_f16(cs_[1], a0, a1, a2, a3, b2, b3);
            ldsm_x4(b0, b1, b2, b3, aK1 + koff);
            mma_f16(cs_[2], a0, a1, a2, a3, b0, b1);
            mma_f16(cs_[3], a0, a1, a2, a3, b2, b3);
        }
        #pragma unroll
        for (int ni = 0; ni < 4; ni++) {
            const int col = wn_s + ni * 8 + 2 * qk;
            float2 s0 = {cs_[ni][0] * scale, cs_[ni][1] * scale};
            float2 s1 = {cs_[ni][2] * scale, cs_[ni][3] * scale};
            *(float2*)&Ss[(wm + qd)     * SSTW + col] = s0;
            *(float2*)&Ss[(wm + qd + 8) * SSTW + col] = s1;
        }
        __syncthreads();

        #pragma unroll
        for (int it = 0; it < 4; it++) {
            const int f   = t + it * 256;
            const int row = f >> 4;
            const int c8  = (f & 15) * 8;
            uint4 u = *(const uint4*)(vb + (size_t)(k0s + row) * DM + c8);
            *(uint4*)(KV + row * QSTH + c8) = u;
        }

        {
            const int sb = g * SSTW + q4 * 16;
            float tmax = -1e30f;
            #pragma unroll
            for (int i = 0; i < 16; i++)
                tmax = fmaxf(tmax, Ss[sb + i]);
            tmax = fmaxf(tmax, __shfl_xor_sync(0xffffffffu, tmax, 1));
            tmax = fmaxf(tmax, __shfl_xor_sync(0xffffffffu, tmax, 2));
            float mnew  = fmaxf(m_r, tmax);
            float alpha = __expf(m_r - mnew);
            float psum  = 0.f;
            const int pb = g * PSTH + q4 * 16;
            #pragma unroll
            for (int i = 0; i < 8; i++) {
                float p0 = __expf(Ss[sb + 2*i]     - mnew);
                float p1 = __expf(Ss[sb + 2*i + 1] - mnew);
                *(__half2*)(Ph + pb + 2*i) = __floats2half2_rn(p0, p1);
                psum += p0 + p1;
            }
            psum += __shfl_xor_sync(0xffffffffu, psum, 1);
            psum += __shfl_xor_sync(0xffffffffu, psum, 2);
            l_r = l_r * alpha + psum;
            m_r = mnew;
            if (q4 == 0) sAlpha[g] = alpha;
        }
        __syncthreads();

        {
            const float al0 = sAlpha[wm + qd];
            const float al1 = sAlpha[wm + qd + 8];
            #pragma unroll
            for (int ni = 0; ni < 8; ni++) {
                o[ni][0] *= al0; o[ni][1] *= al0;
                o[ni][2] *= al1; o[ni][3] *= al1;
            }
        }

        #pragma unroll
        for (int ks = 0; ks < 4; ks++) {
            uint32_t a0, a1, a2, a3;
            ldsm_x4(a0, a1, a2, a3, aP + (uint32_t)ks * 32u);
            const uint32_t vko = (uint32_t)ks * 16u * QSTB;
            #pragma unroll
            for (int np = 0; np < 4; np++) {
                uint32_t b0, b1, b2, b3;
                ldsm_x4_t(b0, b1, b2, b3, aV + vko + (uint32_t)np * 32u);
                mma_f16(o[2*np],   a0, a1, a2, a3, b0, b1);
                mma_f16(o[2*np+1], a0, a1, a2, a3, b2, b3);
            }
        }
    }

    if (q4 == 0) sAlpha[g] = 1.f / l_r;
    __syncthreads();
    const float li0 = sAlpha[wm + qd];
    const float li1 = sAlpha[wm + qd + 8];
    #pragma unroll
    for (int ni = 0; ni < 8; ni++) {
        const int col = wn_v + ni * 8 + 2 * qk;
        __half2 h0 = __floats2half2_rn(o[ni][0] * li0, o[ni][1] * li0);
        __half2 h1 = __floats2half2_rn(o[ni][2] * li1, o[ni][3] * li1);
        *(__half2*)(O + base + (size_t)(q0 + wm + qd)     * DM + col) = h0;
        *(__half2*)(O + base + (size_t)(q0 + wm + qd + 8) * DM + col) = h1;
    }
}

// ---------------------------------------------------------------------------
extern "C" void kernel_launch(void* const* d_in, const int* in_sizes, int n_in,
                              void* d_out, int out_size)
{
    const float* hidden = (const float*)d_in[0];
    const float* rope   = (const float*)d_in[1];
    const float* Wq     = (const float*)d_in[2];
    const float* Wk     = (const float*)d_in[3];
    const float* Wv     = (const float*)d_in[4];
    const float* Wo     = (const float*)d_in[5];
    const float* nqw    = (const float*)d_in[6];
    const float* nkw    = (const float*)d_in[7];
    float* out = (float*)d_out;

    float *q, *k;
    __half *xh, *kh, *vh, *aoh, *wqh, *wkh, *wvh, *woh;
    cudaGetSymbolAddress((void**)&q,   g_q);
    cudaGetSymbolAddress((void**)&k,   g_k);
    cudaGetSymbolAddress((void**)&xh,  g_xh);
    cudaGetSymbolAddress((void**)&kh,  g_kh);
    cudaGetSymbolAddress((void**)&vh,  g_vh);
    cudaGetSymbolAddress((void**)&aoh, g_aoh);
    cudaGetSymbolAddress((void**)&wqh, g_wqh);
    cudaGetSymbolAddress((void**)&wkh, g_wkh);
    cudaGetSymbolAddress((void**)&wvh, g_wvh);
    cudaGetSymbolAddress((void**)&woh, g_woh);

    const int nX4 = MROWS * DM / 4;
    const int nW4 = DM * DM / 4;
    cvt_f32_f16<<<(nX4 + 255) / 256, 256>>>(hidden, xh, nX4);
    cvt_f32_f16<<<(nW4 + 255) / 256, 256>>>(Wq, wqh, nW4);
    cvt_f32_f16<<<(nW4 + 255) / 256, 256>>>(Wk, wkh, nW4);
    cvt_f32_f16<<<(nW4 + 255) / 256, 256>>>(Wv, wvh, nW4);
    cvt_f32_f16<<<(nW4 + 255) / 256, 256>>>(Wo, woh, nW4);

    cudaFuncSetAttribute(f16_gemm_kernel, cudaFuncAttributeMaxDynamicSharedMemorySize, GEMM_SMEM);
    cudaFuncSetAttribute(attn_kernel, cudaFuncAttributeMaxDynamicSharedMemorySize, ATT_SMEM);

    // Fused QKV projection: q,k -> fp32; v -> fp16 directly
    f16_gemm_kernel<<<dim3(72, 16), 256, GEMM_SMEM>>>(xh, wqh, wkh, wvh, q, k, vh);

    // Norm+RoPE: q,k fp32 -> fp16 (q-hat into xh)
    norm_rope_kernel<<<dim3(MROWS, NH), 128>>>(q, k, xh, kh, rope, nqw, nkw);

    attn_kernel<<<dim3(SSEQ/64, BB*NH), 256, ATT_SMEM>>>(xh, kh, vh, aoh);

    // Output projection (wsel==0 path -> fp32 out; Yc unused)
    f16_gemm_kernel<<<dim3(24, 16), 256, GEMM_SMEM>>>(aoh, woh, woh, woh, out, out, aoh);
}

// round 10
// speedup vs baseline: 2.5048x; 1.0107x over previous
#include <cuda_runtime.h>
#include <cuda_fp16.h>
#include <math.h>
#include <stdint.h>

#define DM 3072
#define BB 2
#define SSEQ 1024
#define NH 24
#define HD 128
#define MROWS (BB*SSEQ)   // 2048

// Scratch (device globals: no allocations allowed)
__device__ float  g_q[MROWS*DM];
__device__ float  g_k[MROWS*DM];
__device__ __half g_xh[MROWS*DM];   // hidden fp16, later reused as q-hat fp16
__device__ __half g_kh[MROWS*DM];
__device__ __half g_vh[MROWS*DM];
__device__ __half g_aoh[MROWS*DM];
__device__ __half g_wqh[DM*DM];
__device__ __half g_wkh[DM*DM];
__device__ __half g_wvh[DM*DM];
__device__ __half g_woh[DM*DM];

__device__ __forceinline__ uint32_t smem_u32(const void* p) {
    uint32_t a;
    asm("{ .reg .u64 t; cvta.to.shared.u64 t, %1; cvt.u32.u64 %0, t; }"
        : "=r"(a) : "l"(p));
    return a;
}

__device__ __forceinline__ float fexp2(float x) {
    float y;
    asm("ex2.approx.f32 %0, %1;" : "=f"(y) : "f"(x));
    return y;
}

__device__ __forceinline__ uint32_t h2exp2_bits(uint32_t x) {
    uint32_t y;
    asm("ex2.approx.f16x2 %0, %1;" : "=r"(y) : "r"(x));
    return y;
}

__device__ __forceinline__ void mma_f16(float c[4],
    uint32_t a0, uint32_t a1, uint32_t a2, uint32_t a3,
    uint32_t b0, uint32_t b1)
{
    asm volatile(
        "mma.sync.aligned.m16n8k16.row.col.f32.f16.f16.f32 "
        "{%0,%1,%2,%3}, {%4,%5,%6,%7}, {%8,%9}, {%0,%1,%2,%3};"
        : "+f"(c[0]), "+f"(c[1]), "+f"(c[2]), "+f"(c[3])
        : "r"(a0), "r"(a1), "r"(a2), "r"(a3), "r"(b0), "r"(b1));
}

__device__ __forceinline__ void ldsm_x4(
    uint32_t& r0, uint32_t& r1, uint32_t& r2, uint32_t& r3, uint32_t addr)
{
    asm volatile("ldmatrix.sync.aligned.m8n8.x4.shared.b16 {%0,%1,%2,%3}, [%4];"
        : "=r"(r0), "=r"(r1), "=r"(r2), "=r"(r3) : "r"(addr));
}

__device__ __forceinline__ void ldsm_x4_t(
    uint32_t& r0, uint32_t& r1, uint32_t& r2, uint32_t& r3, uint32_t addr)
{
    asm volatile("ldmatrix.sync.aligned.m8n8.x4.trans.shared.b16 {%0,%1,%2,%3}, [%4];"
        : "=r"(r0), "=r"(r1), "=r"(r2), "=r"(r3) : "r"(addr));
}

__device__ __forceinline__ void cp_async16(uint32_t saddr, const void* gptr) {
    asm volatile("cp.async.cg.shared.global [%0], [%1], 16;"
        :: "r"(saddr), "l"(gptr) : "memory");
}
#define CP_COMMIT() asm volatile("cp.async.commit_group;" ::: "memory")
#define CP_WAIT2()  asm volatile("cp.async.wait_group 2;" ::: "memory")

// ---------------------------------------------------------------------------
// fp32 -> fp16 conversions
// ---------------------------------------------------------------------------
__global__ __launch_bounds__(256) void cvt_f32_f16(
    const float* __restrict__ src, __half* __restrict__ dst, int n4)
{
    int i = blockIdx.x * blockDim.x + threadIdx.x;
    if (i < n4) {
        float4 v = ((const float4*)src)[i];
        __half2 h0 = __floats2half2_rn(v.x, v.y);
        __half2 h1 = __floats2half2_rn(v.z, v.w);
        uint2 o;
        o.x = *(uint32_t*)&h0;
        o.y = *(uint32_t*)&h1;
        ((uint2*)dst)[i] = o;
    }
}

// 4 weight matrices in one launch
__global__ __launch_bounds__(256) void cvt4_f32_f16(
    const float* __restrict__ s0, const float* __restrict__ s1,
    const float* __restrict__ s2, const float* __restrict__ s3,
    __half* __restrict__ d0, __half* __restrict__ d1,
    __half* __restrict__ d2, __half* __restrict__ d3, int n4)
{
    int i = blockIdx.x * blockDim.x + threadIdx.x;
    int which = i / n4;
    int j = i - which * n4;
    const float* s = (which == 0) ? s0 : (which == 1) ? s1 : (which == 2) ? s2 : s3;
    __half* d      = (which == 0) ? d0 : (which == 1) ? d1 : (which == 2) ? d2 : d3;
    float4 v = ((const float4*)s)[j];
    __half2 h0 = __floats2half2_rn(v.x, v.y);
    __half2 h1 = __floats2half2_rn(v.z, v.w);
    uint2 o;
    o.x = *(uint32_t*)&h0;
    o.y = *(uint32_t*)&h1;
    ((uint2*)d)[j] = o;
}

// ---------------------------------------------------------------------------
// fp16 GEMM, cp.async 4-stage pipeline (unchanged from R9).
// ---------------------------------------------------------------------------
#define STAGEB 20480
#define NSTAGE 4
#define GEMM_SMEM (NSTAGE * STAGEB)

__global__ __launch_bounds__(256, 2) void f16_gemm_kernel(
    const __half* __restrict__ X,
    const __half* __restrict__ Wa, const __half* __restrict__ Wb, const __half* __restrict__ Wc,
    float* __restrict__ Ya, float* __restrict__ Yb, __half* __restrict__ Yc)
{
    extern __shared__ char smraw[];
    const uint32_t smb = smem_u32(smraw);

    const int t    = threadIdx.x;
    const int lane = t & 31;
    const int w    = t >> 5;
    const int warp_m = (w >> 1) * 32;
    const int warp_n = (w & 1) * 64;
    const int bx   = blockIdx.x;
    const int wsel = bx / 24;
    const __half* W = (wsel == 0) ? Wa : ((wsel == 1) ? Wb : Wc);
    const int bm = blockIdx.y * 128;
    const int bn = (bx - wsel * 24) * 128;

    const int arow = t >> 1;
    const int kh16 = (t & 1) * 16;
    const __half* xp = X + (size_t)(bm + arow) * DM + kh16;
    const __half* wp = W + (size_t)(bn + arow) * DM + kh16;
    const uint32_t srow = (uint32_t)arow * 80u + (uint32_t)kh16 * 2u;

    const int l7 = lane & 7;
    const int aArow = warp_m + ((lane >> 3) & 1) * 8 + l7;
    const int aAkh  = (lane >> 4) * 8;
    uint32_t offA[2];
    #pragma unroll
    for (int mi = 0; mi < 2; mi++)
        offA[mi] = (uint32_t)(aArow + mi * 16) * 80u + (uint32_t)aAkh * 2u;
    const int aBn  = warp_n + (lane >> 4) * 8 + l7;
    const int aBkh = ((lane >> 3) & 1) * 8;
    uint32_t offB[4];
    #pragma unroll
    for (int np = 0; np < 4; np++)
        offB[np] = 10240u + (uint32_t)(aBn + np * 16) * 80u + (uint32_t)aBkh * 2u;

    float c[2][8][4];
    #pragma unroll
    for (int mi = 0; mi < 2; mi++)
        #pragma unroll
        for (int ni = 0; ni < 8; ni++)
            #pragma unroll
            for (int j = 0; j < 4; j++) c[mi][ni][j] = 0.f;

    const int qd = lane >> 2;
    const int qk = lane & 3;
    const int NKT = DM / 32;

    #define ISSUE(kt_, buf_) do { \
        const uint32_t sa = smb + (uint32_t)(buf_) * STAGEB + srow; \
        const __half* xg = xp + (kt_) * 32; \
        const __half* wg = wp + (kt_) * 32; \
        cp_async16(sa,           xg); \
        cp_async16(sa + 16u,     xg + 8); \
        cp_async16(sa + 10240u,      wg); \
        cp_async16(sa + 10240u + 16u, wg + 8); \
    } while (0)

    ISSUE(0, 0); CP_COMMIT();
    ISSUE(1, 1); CP_COMMIT();
    ISSUE(2, 2); CP_COMMIT();

    int buf = 0;
    for (int kt = 0; kt < NKT; kt++) {
        CP_WAIT2();
        __syncthreads();

        const int nkt = kt + 3;
        if (nkt < NKT) {
            const int nbuf = (buf + 3) & 3;
            ISSUE(nkt, nbuf);
        }
        CP_COMMIT();

        const uint32_t st = smb + (uint32_t)buf * STAGEB;
        #pragma unroll
        for (int ks = 0; ks < 2; ks++) {
            const uint32_t koff = (uint32_t)ks * 32u;
            uint32_t a[2][4];
            ldsm_x4(a[0][0], a[0][1], a[0][2], a[0][3], st + offA[0] + koff);
            ldsm_x4(a[1][0], a[1][1], a[1][2], a[1][3], st + offA[1] + koff);
            #pragma unroll
            for (int np = 0; np < 4; np++) {
                uint32_t b0, b1, b2, b3;
                ldsm_x4(b0, b1, b2, b3, st + offB[np] + koff);
                mma_f16(c[0][2*np],   a[0][0], a[0][1], a[0][2], a[0][3], b0, b1);
                mma_f16(c[1][2*np],   a[1][0], a[1][1], a[1][2], a[1][3], b0, b1);
                mma_f16(c[0][2*np+1], a[0][0], a[0][1], a[0][2], a[0][3], b2, b3);
                mma_f16(c[1][2*np+1], a[1][0], a[1][1], a[1][2], a[1][3], b2, b3);
            }
        }
        buf = (buf + 1) & 3;
        __syncthreads();
    }
    #undef ISSUE

    if (wsel < 2) {
        float* Y = wsel ? Yb : Ya;
        #pragma unroll
        for (int mi = 0; mi < 2; mi++) {
            #pragma unroll
            for (int ni = 0; ni < 8; ni++) {
                const int row = bm + warp_m + mi*16 + qd;
                const int col = bn + warp_n + ni*8 + qk*2;
                float2 v0 = {c[mi][ni][0], c[mi][ni][1]};
                float2 v1 = {c[mi][ni][2], c[mi][ni][3]};
                *(float2*)(Y + (size_t)row * DM + col)       = v0;
                *(float2*)(Y + (size_t)(row + 8) * DM + col) = v1;
            }
        }
    } else {
        #pragma unroll
        for (int mi = 0; mi < 2; mi++) {
            #pragma unroll
            for (int ni = 0; ni < 8; ni++) {
                const int row = bm + warp_m + mi*16 + qd;
                const int col = bn + warp_n + ni*8 + qk*2;
                __half2 h0 = __floats2half2_rn(c[mi][ni][0], c[mi][ni][1]);
                __half2 h1 = __floats2half2_rn(c[mi][ni][2], c[mi][ni][3]);
                *(__half2*)(Yc + (size_t)row * DM + col)       = h0;
                *(__half2*)(Yc + (size_t)(row + 8) * DM + col) = h1;
            }
        }
    }
}

// ---------------------------------------------------------------------------
// Fused RMSNorm + RoPE; emits fp16 q-hat/k-hat. One block per (row, h).
// ---------------------------------------------------------------------------
__global__ __launch_bounds__(128) void norm_rope_kernel(
    const float* __restrict__ q, const float* __restrict__ k,
    __half* __restrict__ qh, __half* __restrict__ kh,
    const float* __restrict__ rope,
    const float* __restrict__ wq, const float* __restrict__ wk)
{
    const int row = blockIdx.x;
    const int h   = blockIdx.y;
    const int d   = threadIdx.x;
    const int s   = row & (SSEQ - 1);
    const size_t idx = (size_t)row * DM + h * HD + d;

    __shared__ float sh[128];
    __shared__ float red[4];

    float fr = rope[s * HD + d];
    float cs, sn;
    sincosf(fr, &sn, &cs);

    #pragma unroll
    for (int which = 0; which < 2; which++) {
        const float* src = which ? k : q;
        __half* dst      = which ? kh : qh;
        const float* w   = which ? wk : wq;

        float x = src[idx];
        float ssum = x * x;
        #pragma unroll
        for (int o = 16; o > 0; o >>= 1)
            ssum += __shfl_xor_sync(0xffffffffu, ssum, o);
        if ((d & 31) == 0) red[d >> 5] = ssum;
        __syncthreads();
        float tot = red[0] + red[1] + red[2] + red[3];
        float xn = x * rsqrtf(tot * (1.f/128.f) + 1e-6f) * w[d];
        sh[d] = xn;
        __syncthreads();
        float rot = (d < 64) ? -sh[d + 64] : sh[d - 64];
        dst[idx] = __float2half_rn(xn * cs + rot * sn);
        __syncthreads();
    }
}

// ---------------------------------------------------------------------------
// fp16 flash attention, base-2 softmax with ex2.approx.f16x2.
// ---------------------------------------------------------------------------
#define QSTH 136
#define QSTB (QSTH*2)
#define SSTW 68
#define PSTH 72
#define PSTB (PSTH*2)
#define ATT_SMEM (64*QSTB*2 + 64*SSTW*4 + 64*PSTB + 256)

__global__ __launch_bounds__(256) void attn_kernel(
    const __half* __restrict__ Q, const __half* __restrict__ K,
    const __half* __restrict__ V, __half* __restrict__ O)
{
    extern __shared__ char smraw[];
    __half* Qh = (__half*)smraw;
    __half* KV = Qh + 64 * QSTH;
    float*  Ss = (float*)(KV + 64 * QSTH);
    __half* Ph = (__half*)(Ss + 64 * SSTW);
    float* sAlpha = (float*)(Ph + 64 * PSTH);

    const uint32_t sQ = smem_u32(Qh);
    const uint32_t sK = smem_u32(KV);
    const uint32_t sP = smem_u32(Ph);

    const int t    = threadIdx.x;
    const int lane = t & 31;
    const int w    = t >> 5;
    const int qd   = lane >> 2;
    const int qk   = lane & 3;
    const int wm   = (w >> 1) * 16;
    const int wn_s = (w & 1) * 32;
    const int wn_v = (w & 1) * 64;
    const int g    = t >> 2;
    const int q4   = t & 3;

    const int qt = blockIdx.x;
    const int bh = blockIdx.y;
    const int b  = bh / NH;
    const int h  = bh % NH;
    const size_t base = (size_t)b * SSEQ * DM + (size_t)h * HD;
    const __half* qb = Q + base;
    const __half* kb = K + base;
    const __half* vb = V + base;
    const int q0 = qt * 64;

    const int l7 = lane & 7;
    const int arow = ((lane >> 3) & 1) * 8 + l7;
    const int akh  = (lane >> 4) * 8;
    const uint32_t aQ = sQ + (uint32_t)(wm + arow) * QSTB + (uint32_t)akh * 2u;
    const uint32_t aP = sP + (uint32_t)(wm + arow) * PSTB + (uint32_t)akh * 2u;
    const int bn  = (lane >> 4) * 8 + l7;
    const int bkh = ((lane >> 3) & 1) * 8;
    const uint32_t aK0 = sK + (uint32_t)(wn_s + bn) * QSTB + (uint32_t)bkh * 2u;
    const uint32_t aK1 = aK0 + 16u * QSTB;
    const uint32_t aV = sK + (uint32_t)(((lane >> 3) & 1) * 8 + l7) * QSTB
                      + (uint32_t)(wn_v + (lane >> 4) * 8) * 2u;

    #pragma unroll
    for (int it = 0; it < 4; it++) {
        const int f   = t + it * 256;
        const int row = f >> 4;
        const int c8  = (f & 15) * 8;
        uint4 u = *(const uint4*)(qb + (size_t)(q0 + row) * DM + c8);
        *(uint4*)(Qh + row * QSTH + c8) = u;
    }

    float o[8][4];
    #pragma unroll
    for (int ni = 0; ni < 8; ni++)
        #pragma unroll
        for (int j = 0; j < 4; j++) o[ni][j] = 0.f;

    float m_r = -1e30f, l_r = 0.f;
    // scale * log2(e): softmax done in base 2
    const float scale2 = 0.12751744f;

    for (int kt = 0; kt < 16; kt++) {
        const int k0s = kt * 64;
        __syncthreads();

        #pragma unroll
        for (int it = 0; it < 4; it++) {
            const int f   = t + it * 256;
            const int row = f >> 4;
            const int c8  = (f & 15) * 8;
            uint4 u = *(const uint4*)(kb + (size_t)(k0s + row) * DM + c8);
            *(uint4*)(KV + row * QSTH + c8) = u;
        }
        __syncthreads();

        float cs_[4][4];
        #pragma unroll
        for (int ni = 0; ni < 4; ni++)
            #pragma unroll
            for (int j = 0; j < 4; j++) cs_[ni][j] = 0.f;

        #pragma unroll
        for (int ks = 0; ks < 8; ks++) {
            const uint32_t koff = (uint32_t)ks * 32u;
            uint32_t a0, a1, a2, a3, b0, b1, b2, b3;
            ldsm_x4(a0, a1, a2, a3, aQ + koff);
            ldsm_x4(b0, b1, b2, b3, aK0 + koff);
            mma_f16(cs_[0], a0, a1, a2, a3, b0, b1);
            mma_f16(cs_[1], a0, a1, a2, a3, b2, b3);
            ldsm_x4(b0, b1, b2, b3, aK1 + koff);
            mma_f16(cs_[2], a0, a1, a2, a3, b0, b1);
            mma_f16(cs_[3], a0, a1, a2, a3, b2, b3);
        }
        #pragma unroll
        for (int ni = 0; ni < 4; ni++) {
            const int col = wn_s + ni * 8 + 2 * qk;
            float2 s0 = {cs_[ni][0] * scale2, cs_[ni][1] * scale2};
            float2 s1 = {cs_[ni][2] * scale2, cs_[ni][3] * scale2};
            *(float2*)&Ss[(wm + qd)     * SSTW + col] = s0;
            *(float2*)&Ss[(wm + qd + 8) * SSTW + col] = s1;
        }
        __syncthreads();

        #pragma unroll
        for (int it = 0; it < 4; it++) {
            const int f   = t + it * 256;
            const int row = f >> 4;
            const int c8  = (f & 15) * 8;
            uint4 u = *(const uint4*)(vb + (size_t)(k0s + row) * DM + c8);
            *(uint4*)(KV + row * QSTH + c8) = u;
        }

        // Online softmax (base 2), probs via ex2.approx.f16x2
        {
            const int sb = g * SSTW + q4 * 16;
            float tmax = -1e30f;
            #pragma unroll
            for (int i = 0; i < 16; i++)
                tmax = fmaxf(tmax, Ss[sb + i]);
            tmax = fmaxf(tmax, __shfl_xor_sync(0xffffffffu, tmax, 1));
            tmax = fmaxf(tmax, __shfl_xor_sync(0xffffffffu, tmax, 2));
            float mnew  = fmaxf(m_r, tmax);
            float alpha = fexp2(m_r - mnew);
            float psum  = 0.f;
            const int pb = g * PSTH + q4 * 16;
            #pragma unroll
            for (int i = 0; i < 8; i++) {
                float d0 = Ss[sb + 2*i]     - mnew;
                float d1 = Ss[sb + 2*i + 1] - mnew;
                __half2 dh = __floats2half2_rn(d0, d1);
                uint32_t pbits = h2exp2_bits(*(uint32_t*)&dh);
                *(uint32_t*)(Ph + pb + 2*i) = pbits;
                __half2 pv = *(__half2*)&pbits;
                psum += __low2float(pv) + __high2float(pv);
            }
            psum += __shfl_xor_sync(0xffffffffu, psum, 1);
            psum += __shfl_xor_sync(0xffffffffu, psum, 2);
            l_r = l_r * alpha + psum;
            m_r = mnew;
            if (q4 == 0) sAlpha[g] = alpha;
        }
        __syncthreads();

        {
            const float al0 = sAlpha[wm + qd];
            const float al1 = sAlpha[wm + qd + 8];
            #pragma unroll
            for (int ni = 0; ni < 8; ni++) {
                o[ni][0] *= al0; o[ni][1] *= al0;
                o[ni][2] *= al1; o[ni][3] *= al1;
            }
        }

        #pragma unroll
        for (int ks = 0; ks < 4; ks++) {
            uint32_t a0, a1, a2, a3;
            ldsm_x4(a0, a1, a2, a3, aP + (uint32_t)ks * 32u);
            const uint32_t vko = (uint32_t)ks * 16u * QSTB;
            #pragma unroll
            for (int np = 0; np < 4; np++) {
                uint32_t b0, b1, b2, b3;
                ldsm_x4_t(b0, b1, b2, b3, aV + vko + (uint32_t)np * 32u);
                mma_f16(o[2*np],   a0, a1, a2, a3, b0, b1);
                mma_f16(o[2*np+1], a0, a1, a2, a3, b2, b3);
            }
        }
    }

    if (q4 == 0) sAlpha[g] = 1.f / l_r;
    __syncthreads();
    const float li0 = sAlpha[wm + qd];
    const float li1 = sAlpha[wm + qd + 8];
    #pragma unroll
    for (int ni = 0; ni < 8; ni++) {
        const int col = wn_v + ni * 8 + 2 * qk;
        __half2 h0 = __floats2half2_rn(o[ni][0] * li0, o[ni][1] * li0);
        __half2 h1 = __floats2half2_rn(o[ni][2] * li1, o[ni][3] * li1);
        *(__half2*)(O + base + (size_t)(q0 + wm + qd)     * DM + col) = h0;
        *(__half2*)(O + base + (size_t)(q0 + wm + qd + 8) * DM + col) = h1;
    }
}

// ---------------------------------------------------------------------------
extern "C" void kernel_launch(void* const* d_in, const int* in_sizes, int n_in,
                              void* d_out, int out_size)
{
    const float* hidden = (const float*)d_in[0];
    const float* rope   = (const float*)d_in[1];
    const float* Wq     = (const float*)d_in[2];
    const float* Wk     = (const float*)d_in[3];
    const float* Wv     = (const float*)d_in[4];
    const float* Wo     = (const float*)d_in[5];
    const float* nqw    = (const float*)d_in[6];
    const float* nkw    = (const float*)d_in[7];
    float* out = (float*)d_out;

    float *q, *k;
    __half *xh, *kh, *vh, *aoh, *wqh, *wkh, *wvh, *woh;
    cudaGetSymbolAddress((void**)&q,   g_q);
    cudaGetSymbolAddress((void**)&k,   g_k);
    cudaGetSymbolAddress((void**)&xh,  g_xh);
    cudaGetSymbolAddress((void**)&kh,  g_kh);
    cudaGetSymbolAddress((void**)&vh,  g_vh);
    cudaGetSymbolAddress((void**)&aoh, g_aoh);
    cudaGetSymbolAddress((void**)&wqh, g_wqh);
    cudaGetSymbolAddress((void**)&wkh, g_wkh);
    cudaGetSymbolAddress((void**)&wvh, g_wvh);
    cudaGetSymbolAddress((void**)&woh, g_woh);

    const int nX4 = MROWS * DM / 4;
    const int nW4 = DM * DM / 4;
    cvt_f32_f16<<<(nX4 + 255) / 256, 256>>>(hidden, xh, nX4);
    cvt4_f32_f16<<<(4 * nW4 + 255) / 256, 256>>>(Wq, Wk, Wv, Wo,
                                                 wqh, wkh, wvh, woh, nW4);

    cudaFuncSetAttribute(f16_gemm_kernel, cudaFuncAttributeMaxDynamicSharedMemorySize, GEMM_SMEM);
    cudaFuncSetAttribute(attn_kernel, cudaFuncAttributeMaxDynamicSharedMemorySize, ATT_SMEM);

    // Fused QKV projection: q,k -> fp32; v -> fp16 directly
    f16_gemm_kernel<<<dim3(72, 16), 256, GEMM_SMEM>>>(xh, wqh, wkh, wvh, q, k, vh);

    // Norm+RoPE: q,k fp32 -> fp16 (q-hat into xh)
    norm_rope_kernel<<<dim3(MROWS, NH), 128>>>(q, k, xh, kh, rope, nqw, nkw);

    attn_kernel<<<dim3(SSEQ/64, BB*NH), 256, ATT_SMEM>>>(xh, kh, vh, aoh);

    // Output projection (wsel==0 path -> fp32 out; Yc unused)
    f16_gemm_kernel<<<dim3(24, 16), 256, GEMM_SMEM>>>(aoh, woh, woh, woh, out, out, aoh);
}

// round 11
// speedup vs baseline: 2.6998x; 1.0778x over previous
#include <cuda_runtime.h>
#include <cuda_fp16.h>
#include <math.h>
#include <stdint.h>

#define DM 3072
#define BB 2
#define SSEQ 1024
#define NH 24
#define HD 128
#define MROWS (BB*SSEQ)   // 2048

// Scratch (device globals: no allocations allowed)
__device__ float  g_q[MROWS*DM];
__device__ float  g_k[MROWS*DM];
__device__ __half g_xh[MROWS*DM];   // hidden fp16, later reused as q-hat fp16
__device__ __half g_kh[MROWS*DM];
__device__ __half g_vh[MROWS*DM];
__device__ __half g_aoh[MROWS*DM];
__device__ __half g_wqh[DM*DM];
__device__ __half g_wkh[DM*DM];
__device__ __half g_wvh[DM*DM];
__device__ __half g_woh[DM*DM];

__device__ __forceinline__ uint32_t smem_u32(const void* p) {
    uint32_t a;
    asm("{ .reg .u64 t; cvta.to.shared.u64 t, %1; cvt.u32.u64 %0, t; }"
        : "=r"(a) : "l"(p));
    return a;
}

__device__ __forceinline__ float fexp2(float x) {
    float y;
    asm("ex2.approx.f32 %0, %1;" : "=f"(y) : "f"(x));
    return y;
}

__device__ __forceinline__ uint32_t h2exp2_bits(uint32_t x) {
    uint32_t y;
    asm("ex2.approx.f16x2 %0, %1;" : "=r"(y) : "r"(x));
    return y;
}

__device__ __forceinline__ void mma_f16(float c[4],
    uint32_t a0, uint32_t a1, uint32_t a2, uint32_t a3,
    uint32_t b0, uint32_t b1)
{
    asm volatile(
        "mma.sync.aligned.m16n8k16.row.col.f32.f16.f16.f32 "
        "{%0,%1,%2,%3}, {%4,%5,%6,%7}, {%8,%9}, {%0,%1,%2,%3};"
        : "+f"(c[0]), "+f"(c[1]), "+f"(c[2]), "+f"(c[3])
        : "r"(a0), "r"(a1), "r"(a2), "r"(a3), "r"(b0), "r"(b1));
}

__device__ __forceinline__ void ldsm_x4(
    uint32_t& r0, uint32_t& r1, uint32_t& r2, uint32_t& r3, uint32_t addr)
{
    asm volatile("ldmatrix.sync.aligned.m8n8.x4.shared.b16 {%0,%1,%2,%3}, [%4];"
        : "=r"(r0), "=r"(r1), "=r"(r2), "=r"(r3) : "r"(addr));
}

__device__ __forceinline__ void ldsm_x4_t(
    uint32_t& r0, uint32_t& r1, uint32_t& r2, uint32_t& r3, uint32_t addr)
{
    asm volatile("ldmatrix.sync.aligned.m8n8.x4.trans.shared.b16 {%0,%1,%2,%3}, [%4];"
        : "=r"(r0), "=r"(r1), "=r"(r2), "=r"(r3) : "r"(addr));
}

__device__ __forceinline__ void cp_async16(uint32_t saddr, const void* gptr) {
    asm volatile("cp.async.cg.shared.global [%0], [%1], 16;"
        :: "r"(saddr), "l"(gptr) : "memory");
}
#define CP_COMMIT() asm volatile("cp.async.commit_group;" ::: "memory")
#define CP_WAIT2()  asm volatile("cp.async.wait_group 2;" ::: "memory")

// ---------------------------------------------------------------------------
// fp32 -> fp16 conversions
// ---------------------------------------------------------------------------
__global__ __launch_bounds__(256) void cvt_f32_f16(
    const float* __restrict__ src, __half* __restrict__ dst, int n4)
{
    int i = blockIdx.x * blockDim.x + threadIdx.x;
    if (i < n4) {
        float4 v = ((const float4*)src)[i];
        __half2 h0 = __floats2half2_rn(v.x, v.y);
        __half2 h1 = __floats2half2_rn(v.z, v.w);
        uint2 o;
        o.x = *(uint32_t*)&h0;
        o.y = *(uint32_t*)&h1;
        ((uint2*)dst)[i] = o;
    }
}

__global__ __launch_bounds__(256) void cvt4_f32_f16(
    const float* __restrict__ s0, const float* __restrict__ s1,
    const float* __restrict__ s2, const float* __restrict__ s3,
    __half* __restrict__ d0, __half* __restrict__ d1,
    __half* __restrict__ d2, __half* __restrict__ d3, int n4)
{
    int i = blockIdx.x * blockDim.x + threadIdx.x;
    int which = i / n4;
    int j = i - which * n4;
    const float* s = (which == 0) ? s0 : (which == 1) ? s1 : (which == 2) ? s2 : s3;
    __half* d      = (which == 0) ? d0 : (which == 1) ? d1 : (which == 2) ? d2 : d3;
    float4 v = ((const float4*)s)[j];
    __half2 h0 = __floats2half2_rn(v.x, v.y);
    __half2 h1 = __floats2half2_rn(v.z, v.w);
    uint2 o;
    o.x = *(uint32_t*)&h0;
    o.y = *(uint32_t*)&h1;
    ((uint2*)d)[j] = o;
}

// ---------------------------------------------------------------------------
// fp16 GEMM, cp.async 4-stage pipeline (unchanged from R9).
// ---------------------------------------------------------------------------
#define STAGEB 20480
#define NSTAGE 4
#define GEMM_SMEM (NSTAGE * STAGEB)

__global__ __launch_bounds__(256, 2) void f16_gemm_kernel(
    const __half* __restrict__ X,
    const __half* __restrict__ Wa, const __half* __restrict__ Wb, const __half* __restrict__ Wc,
    float* __restrict__ Ya, float* __restrict__ Yb, __half* __restrict__ Yc)
{
    extern __shared__ char smraw[];
    const uint32_t smb = smem_u32(smraw);

    const int t    = threadIdx.x;
    const int lane = t & 31;
    const int w    = t >> 5;
    const int warp_m = (w >> 1) * 32;
    const int warp_n = (w & 1) * 64;
    const int bx   = blockIdx.x;
    const int wsel = bx / 24;
    const __half* W = (wsel == 0) ? Wa : ((wsel == 1) ? Wb : Wc);
    const int bm = blockIdx.y * 128;
    const int bn = (bx - wsel * 24) * 128;

    const int arow = t >> 1;
    const int kh16 = (t & 1) * 16;
    const __half* xp = X + (size_t)(bm + arow) * DM + kh16;
    const __half* wp = W + (size_t)(bn + arow) * DM + kh16;
    const uint32_t srow = (uint32_t)arow * 80u + (uint32_t)kh16 * 2u;

    const int l7 = lane & 7;
    const int aArow = warp_m + ((lane >> 3) & 1) * 8 + l7;
    const int aAkh  = (lane >> 4) * 8;
    uint32_t offA[2];
    #pragma unroll
    for (int mi = 0; mi < 2; mi++)
        offA[mi] = (uint32_t)(aArow + mi * 16) * 80u + (uint32_t)aAkh * 2u;
    const int aBn  = warp_n + (lane >> 4) * 8 + l7;
    const int aBkh = ((lane >> 3) & 1) * 8;
    uint32_t offB[4];
    #pragma unroll
    for (int np = 0; np < 4; np++)
        offB[np] = 10240u + (uint32_t)(aBn + np * 16) * 80u + (uint32_t)aBkh * 2u;

    float c[2][8][4];
    #pragma unroll
    for (int mi = 0; mi < 2; mi++)
        #pragma unroll
        for (int ni = 0; ni < 8; ni++)
            #pragma unroll
            for (int j = 0; j < 4; j++) c[mi][ni][j] = 0.f;

    const int qd = lane >> 2;
    const int qk = lane & 3;
    const int NKT = DM / 32;

    #define ISSUE(kt_, buf_) do { \
        const uint32_t sa = smb + (uint32_t)(buf_) * STAGEB + srow; \
        const __half* xg = xp + (kt_) * 32; \
        const __half* wg = wp + (kt_) * 32; \
        cp_async16(sa,           xg); \
        cp_async16(sa + 16u,     xg + 8); \
        cp_async16(sa + 10240u,      wg); \
        cp_async16(sa + 10240u + 16u, wg + 8); \
    } while (0)

    ISSUE(0, 0); CP_COMMIT();
    ISSUE(1, 1); CP_COMMIT();
    ISSUE(2, 2); CP_COMMIT();

    int buf = 0;
    for (int kt = 0; kt < NKT; kt++) {
        CP_WAIT2();
        __syncthreads();

        const int nkt = kt + 3;
        if (nkt < NKT) {
            const int nbuf = (buf + 3) & 3;
            ISSUE(nkt, nbuf);
        }
        CP_COMMIT();

        const uint32_t st = smb + (uint32_t)buf * STAGEB;
        #pragma unroll
        for (int ks = 0; ks < 2; ks++) {
            const uint32_t koff = (uint32_t)ks * 32u;
            uint32_t a[2][4];
            ldsm_x4(a[0][0], a[0][1], a[0][2], a[0][3], st + offA[0] + koff);
            ldsm_x4(a[1][0], a[1][1], a[1][2], a[1][3], st + offA[1] + koff);
            #pragma unroll
            for (int np = 0; np < 4; np++) {
                uint32_t b0, b1, b2, b3;
                ldsm_x4(b0, b1, b2, b3, st + offB[np] + koff);
                mma_f16(c[0][2*np],   a[0][0], a[0][1], a[0][2], a[0][3], b0, b1);
                mma_f16(c[1][2*np],   a[1][0], a[1][1], a[1][2], a[1][3], b0, b1);
                mma_f16(c[0][2*np+1], a[0][0], a[0][1], a[0][2], a[0][3], b2, b3);
                mma_f16(c[1][2*np+1], a[1][0], a[1][1], a[1][2], a[1][3], b2, b3);
            }
        }
        buf = (buf + 1) & 3;
        __syncthreads();
    }
    #undef ISSUE

    if (wsel < 2) {
        float* Y = wsel ? Yb : Ya;
        #pragma unroll
        for (int mi = 0; mi < 2; mi++) {
            #pragma unroll
            for (int ni = 0; ni < 8; ni++) {
                const int row = bm + warp_m + mi*16 + qd;
                const int col = bn + warp_n + ni*8 + qk*2;
                float2 v0 = {c[mi][ni][0], c[mi][ni][1]};
                float2 v1 = {c[mi][ni][2], c[mi][ni][3]};
                *(float2*)(Y + (size_t)row * DM + col)       = v0;
                *(float2*)(Y + (size_t)(row + 8) * DM + col) = v1;
            }
        }
    } else {
        #pragma unroll
        for (int mi = 0; mi < 2; mi++) {
            #pragma unroll
            for (int ni = 0; ni < 8; ni++) {
                const int row = bm + warp_m + mi*16 + qd;
                const int col = bn + warp_n + ni*8 + qk*2;
                __half2 h0 = __floats2half2_rn(c[mi][ni][0], c[mi][ni][1]);
                __half2 h1 = __floats2half2_rn(c[mi][ni][2], c[mi][ni][3]);
                *(__half2*)(Yc + (size_t)row * DM + col)       = h0;
                *(__half2*)(Yc + (size_t)(row + 8) * DM + col) = h1;
            }
        }
    }
}

// ---------------------------------------------------------------------------
// Fused RMSNorm + RoPE; emits fp16 q-hat/k-hat. One block per (row, h).
// ---------------------------------------------------------------------------
__global__ __launch_bounds__(128) void norm_rope_kernel(
    const float* __restrict__ q, const float* __restrict__ k,
    __half* __restrict__ qh, __half* __restrict__ kh,
    const float* __restrict__ rope,
    const float* __restrict__ wq, const float* __restrict__ wk)
{
    const int row = blockIdx.x;
    const int h   = blockIdx.y;
    const int d   = threadIdx.x;
    const int s   = row & (SSEQ - 1);
    const size_t idx = (size_t)row * DM + h * HD + d;

    __shared__ float sh[128];
    __shared__ float red[4];

    float fr = rope[s * HD + d];
    float cs, sn;
    sincosf(fr, &sn, &cs);

    #pragma unroll
    for (int which = 0; which < 2; which++) {
        const float* src = which ? k : q;
        __half* dst      = which ? kh : qh;
        const float* w   = which ? wk : wq;

        float x = src[idx];
        float ssum = x * x;
        #pragma unroll
        for (int o = 16; o > 0; o >>= 1)
            ssum += __shfl_xor_sync(0xffffffffu, ssum, o);
        if ((d & 31) == 0) red[d >> 5] = ssum;
        __syncthreads();
        float tot = red[0] + red[1] + red[2] + red[3];
        float xn = x * rsqrtf(tot * (1.f/128.f) + 1e-6f) * w[d];
        sh[d] = xn;
        __syncthreads();
        float rot = (d < 64) ? -sh[d + 64] : sh[d - 64];
        dst[idx] = __float2half_rn(xn * cs + rot * sn);
        __syncthreads();
    }
}

// ---------------------------------------------------------------------------
// fp16 flash attention, FA2-style register softmax.
// 128 threads (4 warps); q-tile 64 (16 rows/warp, full 64-col score rows);
// k-tile 128 (two 64-key sub-tiles per load, one sync pair per 128 keys).
// Smem: Qh[64][136], Kh[128][136], Vh[128][136]. No S/P smem.
// ---------------------------------------------------------------------------
#define STH 136
#define STB (STH*2)
#define ATT_SMEM ((64 + 128 + 128) * STH * 2)   // 87040

__global__ __launch_bounds__(128) void attn_kernel(
    const __half* __restrict__ Q, const __half* __restrict__ K,
    const __half* __restrict__ V, __half* __restrict__ O)
{
    extern __shared__ char smraw[];
    __half* Qh = (__half*)smraw;
    __half* Kh = Qh + 64 * STH;
    __half* Vh = Kh + 128 * STH;
    const uint32_t sQ = smem_u32(Qh);
    const uint32_t sK = smem_u32(Kh);
    const uint32_t sV = smem_u32(Vh);

    const int t    = threadIdx.x;
    const int lane = t & 31;
    const int w    = t >> 5;        // 0..3
    const int qd   = lane >> 2;
    const int qk   = lane & 3;
    const int wm   = w * 16;        // warp's q-row base

    const int qt = blockIdx.x;
    const int bh = blockIdx.y;
    const int b  = bh / NH;
    const int h  = bh % NH;
    const size_t base = (size_t)b * SSEQ * DM + (size_t)h * HD;
    const __half* qb = Q + base;
    const __half* kb = K + base;
    const __half* vb = V + base;
    const int q0 = qt * 64;

    // fragment addresses
    const int l7   = lane & 7;
    const int arow = ((lane >> 3) & 1) * 8 + l7;
    const int akh  = (lane >> 4) * 8;
    const uint32_t aQ = sQ + (uint32_t)(wm + arow) * STB + (uint32_t)akh * 2u;
    const int bnr  = (lane >> 4) * 8 + l7;
    const int bkh  = ((lane >> 3) & 1) * 8;
    const uint32_t aK = sK + (uint32_t)bnr * STB + (uint32_t)bkh * 2u;
    const uint32_t aV = sV + (uint32_t)arow * STB + (uint32_t)((lane >> 4) * 8) * 2u;

    // Load Q tile: 64 rows x 128 halves
    #pragma unroll
    for (int it = 0; it < 8; it++) {
        const int f   = t + it * 128;
        const int row = f >> 4;
        const int c8  = (f & 15) * 8;
        uint4 u = *(const uint4*)(qb + (size_t)(q0 + row) * DM + c8);
        *(uint4*)(Qh + row * STH + c8) = u;
    }

    float o[16][4];
    #pragma unroll
    for (int ni = 0; ni < 16; ni++)
        #pragma unroll
        for (int j = 0; j < 4; j++) o[ni][j] = 0.f;

    float m0 = -1e30f, m1 = -1e30f, l0 = 0.f, l1 = 0.f;
    const float scale2 = 0.12751744f;   // (1/sqrt(128)) * log2(e)

    for (int kt = 0; kt < 8; kt++) {
        const int k0s = kt * 128;
        __syncthreads();   // prior sub-iters' K/V reads complete (covers Q on kt=0)

        // Load K and V tiles (128 rows x 128 halves each)
        #pragma unroll
        for (int it = 0; it < 16; it++) {
            const int f   = t + it * 128;
            const int row = f >> 4;
            const int c8  = (f & 15) * 8;
            const size_t g = (size_t)(k0s + row) * DM + c8;
            *(uint4*)(Kh + row * STH + c8) = *(const uint4*)(kb + g);
            *(uint4*)(Vh + row * STH + c8) = *(const uint4*)(vb + g);
        }
        __syncthreads();

        #pragma unroll
        for (int half = 0; half < 2; half++) {
            const uint32_t hrow = (uint32_t)(half * 64) * STB;

            // S[16x64] = Q_warp @ K_half^T
            float cs[8][4];
            #pragma unroll
            for (int ni = 0; ni < 8; ni++)
                #pragma unroll
                for (int j = 0; j < 4; j++) cs[ni][j] = 0.f;

            #pragma unroll
            for (int ks = 0; ks < 8; ks++) {
                const uint32_t koff = (uint32_t)ks * 32u;
                uint32_t a0, a1, a2, a3;
                ldsm_x4(a0, a1, a2, a3, aQ + koff);
                #pragma unroll
                for (int p = 0; p < 4; p++) {
                    uint32_t b0, b1, b2, b3;
                    ldsm_x4(b0, b1, b2, b3, aK + hrow + (uint32_t)(p * 16) * STB + koff);
                    mma_f16(cs[2*p],   a0, a1, a2, a3, b0, b1);
                    mma_f16(cs[2*p+1], a0, a1, a2, a3, b2, b3);
                }
            }
            #pragma unroll
            for (int ni = 0; ni < 8; ni++) {
                cs[ni][0] *= scale2; cs[ni][1] *= scale2;
                cs[ni][2] *= scale2; cs[ni][3] *= scale2;
            }

            // Row stats (rows qd and qd+8), warp-local
            float t0 = -1e30f, t1 = -1e30f;
            #pragma unroll
            for (int ni = 0; ni < 8; ni++) {
                t0 = fmaxf(t0, fmaxf(cs[ni][0], cs[ni][1]));
                t1 = fmaxf(t1, fmaxf(cs[ni][2], cs[ni][3]));
            }
            t0 = fmaxf(t0, __shfl_xor_sync(0xffffffffu, t0, 1));
            t0 = fmaxf(t0, __shfl_xor_sync(0xffffffffu, t0, 2));
            t1 = fmaxf(t1, __shfl_xor_sync(0xffffffffu, t1, 1));
            t1 = fmaxf(t1, __shfl_xor_sync(0xffffffffu, t1, 2));
            const float mn0 = fmaxf(m0, t0);
            const float mn1 = fmaxf(m1, t1);
            const float al0 = fexp2(m0 - mn0);
            const float al1 = fexp2(m1 - mn1);

            // exp (base-2, f16x2); P fragments built directly in registers
            uint32_t plo[8], phi[8];
            float ps0 = 0.f, ps1 = 0.f;
            #pragma unroll
            for (int ni = 0; ni < 8; ni++) {
                __half2 d0 = __floats2half2_rn(cs[ni][0] - mn0, cs[ni][1] - mn0);
                __half2 d1 = __floats2half2_rn(cs[ni][2] - mn1, cs[ni][3] - mn1);
                plo[ni] = h2exp2_bits(*(uint32_t*)&d0);
                phi[ni] = h2exp2_bits(*(uint32_t*)&d1);
                __half2 p0 = *(__half2*)&plo[ni];
                __half2 p1 = *(__half2*)&phi[ni];
                ps0 += __low2float(p0) + __high2float(p0);
                ps1 += __low2float(p1) + __high2float(p1);
            }
            ps0 += __shfl_xor_sync(0xffffffffu, ps0, 1);
            ps0 += __shfl_xor_sync(0xffffffffu, ps0, 2);
            ps1 += __shfl_xor_sync(0xffffffffu, ps1, 1);
            ps1 += __shfl_xor_sync(0xffffffffu, ps1, 2);
            l0 = l0 * al0 + ps0;
            l1 = l1 * al1 + ps1;
            m0 = mn0;
            m1 = mn1;

            // Rescale accumulators
            #pragma unroll
            for (int ni = 0; ni < 16; ni++) {
                o[ni][0] *= al0; o[ni][1] *= al0;
                o[ni][2] *= al1; o[ni][3] *= al1;
            }

            // PV: O[16x128] += P[16x64] @ V_half[64x128]
            #pragma unroll
            for (int kc = 0; kc < 4; kc++) {
                const uint32_t a0 = plo[2*kc],   a1 = phi[2*kc];
                const uint32_t a2 = plo[2*kc+1], a3 = phi[2*kc+1];
                const uint32_t vro = hrow + (uint32_t)(kc * 16) * STB;
                #pragma unroll
                for (int np = 0; np < 8; np++) {
                    uint32_t b0, b1, b2, b3;
                    ldsm_x4_t(b0, b1, b2, b3, aV + vro + (uint32_t)np * 32u);
                    mma_f16(o[2*np],   a0, a1, a2, a3, b0, b1);
                    mma_f16(o[2*np+1], a0, a1, a2, a3, b2, b3);
                }
            }
        }
    }

    // Epilogue: normalize + write fp16
    const float inv0 = 1.f / l0;
    const float inv1 = 1.f / l1;
    #pragma unroll
    for (int ni = 0; ni < 16; ni++) {
        const int col = ni * 8 + 2 * qk;
        __half2 h0 = __floats2half2_rn(o[ni][0] * inv0, o[ni][1] * inv0);
        __half2 h1 = __floats2half2_rn(o[ni][2] * inv1, o[ni][3] * inv1);
        *(__half2*)(O + base + (size_t)(q0 + wm + qd)     * DM + col) = h0;
        *(__half2*)(O + base + (size_t)(q0 + wm + qd + 8) * DM + col) = h1;
    }
}

// ---------------------------------------------------------------------------
extern "C" void kernel_launch(void* const* d_in, const int* in_sizes, int n_in,
                              void* d_out, int out_size)
{
    const float* hidden = (const float*)d_in[0];
    const float* rope   = (const float*)d_in[1];
    const float* Wq     = (const float*)d_in[2];
    const float* Wk     = (const float*)d_in[3];
    const float* Wv     = (const float*)d_in[4];
    const float* Wo     = (const float*)d_in[5];
    const float* nqw    = (const float*)d_in[6];
    const float* nkw    = (const float*)d_in[7];
    float* out = (float*)d_out;

    float *q, *k;
    __half *xh, *kh, *vh, *aoh, *wqh, *wkh, *wvh, *woh;
    cudaGetSymbolAddress((void**)&q,   g_q);
    cudaGetSymbolAddress((void**)&k,   g_k);
    cudaGetSymbolAddress((void**)&xh,  g_xh);
    cudaGetSymbolAddress((void**)&kh,  g_kh);
    cudaGetSymbolAddress((void**)&vh,  g_vh);
    cudaGetSymbolAddress((void**)&aoh, g_aoh);
    cudaGetSymbolAddress((void**)&wqh, g_wqh);
    cudaGetSymbolAddress((void**)&wkh, g_wkh);
    cudaGetSymbolAddress((void**)&wvh, g_wvh);
    cudaGetSymbolAddress((void**)&woh, g_woh);

    const int nX4 = MROWS * DM / 4;
    const int nW4 = DM * DM / 4;
    cvt_f32_f16<<<(nX4 + 255) / 256, 256>>>(hidden, xh, nX4);
    cvt4_f32_f16<<<(4 * nW4 + 255) / 256, 256>>>(Wq, Wk, Wv, Wo,
                                                 wqh, wkh, wvh, woh, nW4);

    cudaFuncSetAttribute(f16_gemm_kernel, cudaFuncAttributeMaxDynamicSharedMemorySize, GEMM_SMEM);
    cudaFuncSetAttribute(attn_kernel, cudaFuncAttributeMaxDynamicSharedMemorySize, ATT_SMEM);

    // Fused QKV projection: q,k -> fp32; v -> fp16 directly
    f16_gemm_kernel<<<dim3(72, 16), 256, GEMM_SMEM>>>(xh, wqh, wkh, wvh, q, k, vh);

    // Norm+RoPE: q,k fp32 -> fp16 (q-hat into xh)
    norm_rope_kernel<<<dim3(MROWS, NH), 128>>>(q, k, xh, kh, rope, nqw, nkw);

    attn_kernel<<<dim3(SSEQ/64, BB*NH), 128, ATT_SMEM>>>(xh, kh, vh, aoh);

    // Output projection (wsel==0 path -> fp32 out; Yc unused)
    f16_gemm_kernel<<<dim3(24, 16), 256, GEMM_SMEM>>>(aoh, woh, woh, woh, out, out, aoh);
}

// round 12
// speedup vs baseline: 2.8015x; 1.0377x over previous
#include <cuda_runtime.h>
#include <cuda_fp16.h>
#include <math.h>
#include <stdint.h>

#define DM 3072
#define BB 2
#define SSEQ 1024
#define NH 24
#define HD 128
#define MROWS (BB*SSEQ)   // 2048

// Scratch (device globals: no allocations allowed)
__device__ float  g_q[MROWS*DM];
__device__ float  g_k[MROWS*DM];
__device__ __half g_xh[MROWS*DM];   // hidden fp16, later reused as q-hat fp16
__device__ __half g_kh[MROWS*DM];
__device__ __half g_vh[MROWS*DM];
__device__ __half g_aoh[MROWS*DM];
__device__ __half g_wqh[DM*DM];
__device__ __half g_wkh[DM*DM];
__device__ __half g_wvh[DM*DM];
__device__ __half g_woh[DM*DM];

__device__ __forceinline__ uint32_t smem_u32(const void* p) {
    uint32_t a;
    asm("{ .reg .u64 t; cvta.to.shared.u64 t, %1; cvt.u32.u64 %0, t; }"
        : "=r"(a) : "l"(p));
    return a;
}

__device__ __forceinline__ float fexp2(float x) {
    float y;
    asm("ex2.approx.f32 %0, %1;" : "=f"(y) : "f"(x));
    return y;
}

__device__ __forceinline__ uint32_t h2exp2_bits(uint32_t x) {
    uint32_t y;
    asm("ex2.approx.f16x2 %0, %1;" : "=r"(y) : "r"(x));
    return y;
}

__device__ __forceinline__ void mma_f16(float c[4],
    uint32_t a0, uint32_t a1, uint32_t a2, uint32_t a3,
    uint32_t b0, uint32_t b1)
{
    asm volatile(
        "mma.sync.aligned.m16n8k16.row.col.f32.f16.f16.f32 "
        "{%0,%1,%2,%3}, {%4,%5,%6,%7}, {%8,%9}, {%0,%1,%2,%3};"
        : "+f"(c[0]), "+f"(c[1]), "+f"(c[2]), "+f"(c[3])
        : "r"(a0), "r"(a1), "r"(a2), "r"(a3), "r"(b0), "r"(b1));
}

__device__ __forceinline__ void ldsm_x4(
    uint32_t& r0, uint32_t& r1, uint32_t& r2, uint32_t& r3, uint32_t addr)
{
    asm volatile("ldmatrix.sync.aligned.m8n8.x4.shared.b16 {%0,%1,%2,%3}, [%4];"
        : "=r"(r0), "=r"(r1), "=r"(r2), "=r"(r3) : "r"(addr));
}

__device__ __forceinline__ void ldsm_x4_t(
    uint32_t& r0, uint32_t& r1, uint32_t& r2, uint32_t& r3, uint32_t addr)
{
    asm volatile("ldmatrix.sync.aligned.m8n8.x4.trans.shared.b16 {%0,%1,%2,%3}, [%4];"
        : "=r"(r0), "=r"(r1), "=r"(r2), "=r"(r3) : "r"(addr));
}

__device__ __forceinline__ void cp_async16(uint32_t saddr, const void* gptr) {
    asm volatile("cp.async.cg.shared.global [%0], [%1], 16;"
        :: "r"(saddr), "l"(gptr) : "memory");
}
#define CP_COMMIT() asm volatile("cp.async.commit_group;" ::: "memory")
#define CP_WAIT2()  asm volatile("cp.async.wait_group 2;" ::: "memory")

__device__ __forceinline__ void red_add_f32(float* p, float v) {
    asm volatile("red.global.add.f32 [%0], %1;" :: "l"(p), "f"(v) : "memory");
}

// ---------------------------------------------------------------------------
// fp32 -> fp16 conversions (2-element ILP)
// ---------------------------------------------------------------------------
__global__ __launch_bounds__(256) void cvt_f32_f16(
    const float* __restrict__ src, __half* __restrict__ dst, int n4h)
{
    int i = blockIdx.x * blockDim.x + threadIdx.x;
    if (i < n4h) {
        float4 v0 = ((const float4*)src)[i];
        float4 v1 = ((const float4*)src)[i + n4h];
        __half2 a0 = __floats2half2_rn(v0.x, v0.y);
        __half2 a1 = __floats2half2_rn(v0.z, v0.w);
        __half2 b0 = __floats2half2_rn(v1.x, v1.y);
        __half2 b1 = __floats2half2_rn(v1.z, v1.w);
        uint2 o0 = {*(uint32_t*)&a0, *(uint32_t*)&a1};
        uint2 o1 = {*(uint32_t*)&b0, *(uint32_t*)&b1};
        ((uint2*)dst)[i]       = o0;
        ((uint2*)dst)[i + n4h] = o1;
    }
}

__global__ __launch_bounds__(256) void cvt4_f32_f16(
    const float* __restrict__ s0, const float* __restrict__ s1,
    const float* __restrict__ s2, const float* __restrict__ s3,
    __half* __restrict__ d0, __half* __restrict__ d1,
    __half* __restrict__ d2, __half* __restrict__ d3, int n4)
{
    int base = blockIdx.x * blockDim.x + threadIdx.x;
    #pragma unroll
    for (int r = 0; r < 2; r++) {
        int i = base + r * ((4 * n4) / 2);
        int which = i / n4;
        int j = i - which * n4;
        const float* s = (which == 0) ? s0 : (which == 1) ? s1 : (which == 2) ? s2 : s3;
        __half* d      = (which == 0) ? d0 : (which == 1) ? d1 : (which == 2) ? d2 : d3;
        float4 v = ((const float4*)s)[j];
        __half2 h0 = __floats2half2_rn(v.x, v.y);
        __half2 h1 = __floats2half2_rn(v.z, v.w);
        uint2 o = {*(uint32_t*)&h0, *(uint32_t*)&h1};
        ((uint2*)d)[j] = o;
    }
}

__global__ __launch_bounds__(256) void zero_f32(float* __restrict__ p, int n4)
{
    int i = blockIdx.x * blockDim.x + threadIdx.x;
    if (i < n4) {
        float4 z = {0.f, 0.f, 0.f, 0.f};
        ((float4*)p)[i] = z;
    }
}

// ---------------------------------------------------------------------------
// fp16 GEMM, cp.async 4-stage pipeline, single sync per k-tile.
// k-range split by blockIdx.z (gridDim.z splits). REDUCE: fp32 red.add epilogue.
// ---------------------------------------------------------------------------
#define STAGEB 20480
#define NSTAGE 4
#define GEMM_SMEM (NSTAGE * STAGEB)

template<bool REDUCE>
__global__ __launch_bounds__(256, 2) void f16_gemm_kernel(
    const __half* __restrict__ X,
    const __half* __restrict__ Wa, const __half* __restrict__ Wb, const __half* __restrict__ Wc,
    float* __restrict__ Ya, float* __restrict__ Yb, __half* __restrict__ Yc)
{
    extern __shared__ char smraw[];
    const uint32_t smb = smem_u32(smraw);

    const int t    = threadIdx.x;
    const int lane = t & 31;
    const int w    = t >> 5;
    const int warp_m = (w >> 1) * 32;
    const int warp_n = (w & 1) * 64;
    const int bx   = blockIdx.x;
    const int wsel = bx / 24;
    const __half* W = (wsel == 0) ? Wa : ((wsel == 1) ? Wb : Wc);
    const int bm = blockIdx.y * 128;
    const int bn = (bx - wsel * 24) * 128;

    const int nkt = (DM / 32) / gridDim.z;       // 96 or 48
    const int kh0 = blockIdx.z * nkt * 32;       // k offset in halves

    const int arow = t >> 1;
    const int kh16 = (t & 1) * 16;
    const __half* xp = X + (size_t)(bm + arow) * DM + kh0 + kh16;
    const __half* wp = W + (size_t)(bn + arow) * DM + kh0 + kh16;
    const uint32_t srow = (uint32_t)arow * 80u + (uint32_t)kh16 * 2u;

    const int l7 = lane & 7;
    const int aArow = warp_m + ((lane >> 3) & 1) * 8 + l7;
    const int aAkh  = (lane >> 4) * 8;
    uint32_t offA[2];
    #pragma unroll
    for (int mi = 0; mi < 2; mi++)
        offA[mi] = (uint32_t)(aArow + mi * 16) * 80u + (uint32_t)aAkh * 2u;
    const int aBn  = warp_n + (lane >> 4) * 8 + l7;
    const int aBkh = ((lane >> 3) & 1) * 8;
    uint32_t offB[4];
    #pragma unroll
    for (int np = 0; np < 4; np++)
        offB[np] = 10240u + (uint32_t)(aBn + np * 16) * 80u + (uint32_t)aBkh * 2u;

    float c[2][8][4];
    #pragma unroll
    for (int mi = 0; mi < 2; mi++)
        #pragma unroll
        for (int ni = 0; ni < 8; ni++)
            #pragma unroll
            for (int j = 0; j < 4; j++) c[mi][ni][j] = 0.f;

    const int qd = lane >> 2;
    const int qk = lane & 3;

    #define ISSUE(kt_, buf_) do { \
        const uint32_t sa = smb + (uint32_t)(buf_) * STAGEB + srow; \
        const __half* xg = xp + (kt_) * 32; \
        const __half* wg = wp + (kt_) * 32; \
        cp_async16(sa,           xg); \
        cp_async16(sa + 16u,     xg + 8); \
        cp_async16(sa + 10240u,      wg); \
        cp_async16(sa + 10240u + 16u, wg + 8); \
    } while (0)

    ISSUE(0, 0); CP_COMMIT();
    ISSUE(1, 1); CP_COMMIT();
    ISSUE(2, 2); CP_COMMIT();

    for (int kt = 0; kt < nkt; kt++) {
        const int buf = kt & 3;
        CP_WAIT2();
        __syncthreads();   // stage kt visible to all; prior iter compute done

        const int nk = kt + 3;
        if (nk < nkt) {
            ISSUE(nk, nk & 3);   // overwrites buf (kt-1)&3 — safe past the sync
        }
        CP_COMMIT();

        const uint32_t st = smb + (uint32_t)buf * STAGEB;
        #pragma unroll
        for (int ks = 0; ks < 2; ks++) {
            const uint32_t koff = (uint32_t)ks * 32u;
            uint32_t a[2][4];
            ldsm_x4(a[0][0], a[0][1], a[0][2], a[0][3], st + offA[0] + koff);
            ldsm_x4(a[1][0], a[1][1], a[1][2], a[1][3], st + offA[1] + koff);
            #pragma unroll
            for (int np = 0; np < 4; np++) {
                uint32_t b0, b1, b2, b3;
                ldsm_x4(b0, b1, b2, b3, st + offB[np] + koff);
                mma_f16(c[0][2*np],   a[0][0], a[0][1], a[0][2], a[0][3], b0, b1);
                mma_f16(c[1][2*np],   a[1][0], a[1][1], a[1][2], a[1][3], b0, b1);
                mma_f16(c[0][2*np+1], a[0][0], a[0][1], a[0][2], a[0][3], b2, b3);
                mma_f16(c[1][2*np+1], a[1][0], a[1][1], a[1][2], a[1][3], b2, b3);
            }
        }
    }
    #undef ISSUE

    if (REDUCE) {
        float* Y = Ya;
        #pragma unroll
        for (int mi = 0; mi < 2; mi++) {
            #pragma unroll
            for (int ni = 0; ni < 8; ni++) {
                const int row = bm + warp_m + mi*16 + qd;
                const int col = bn + warp_n + ni*8 + qk*2;
                float* p0 = Y + (size_t)row * DM + col;
                float* p1 = Y + (size_t)(row + 8) * DM + col;
                red_add_f32(p0,     c[mi][ni][0]);
                red_add_f32(p0 + 1, c[mi][ni][1]);
                red_add_f32(p1,     c[mi][ni][2]);
                red_add_f32(p1 + 1, c[mi][ni][3]);
            }
        }
    } else if (wsel < 2) {
        float* Y = wsel ? Yb : Ya;
        #pragma unroll
        for (int mi = 0; mi < 2; mi++) {
            #pragma unroll
            for (int ni = 0; ni < 8; ni++) {
                const int row = bm + warp_m + mi*16 + qd;
                const int col = bn + warp_n + ni*8 + qk*2;
                float2 v0 = {c[mi][ni][0], c[mi][ni][1]};
                float2 v1 = {c[mi][ni][2], c[mi][ni][3]};
                *(float2*)(Y + (size_t)row * DM + col)       = v0;
                *(float2*)(Y + (size_t)(row + 8) * DM + col) = v1;
            }
        }
    } else {
        #pragma unroll
        for (int mi = 0; mi < 2; mi++) {
            #pragma unroll
            for (int ni = 0; ni < 8; ni++) {
                const int row = bm + warp_m + mi*16 + qd;
                const int col = bn + warp_n + ni*8 + qk*2;
                __half2 h0 = __floats2half2_rn(c[mi][ni][0], c[mi][ni][1]);
                __half2 h1 = __floats2half2_rn(c[mi][ni][2], c[mi][ni][3]);
                *(__half2*)(Yc + (size_t)row * DM + col)       = h0;
                *(__half2*)(Yc + (size_t)(row + 8) * DM + col) = h1;
            }
        }
    }
}

// ---------------------------------------------------------------------------
// Fused RMSNorm + RoPE v2: warp-per-head, block-shared sincos, no block
// reductions. grid (MROWS, NH/8), block 256 (8 warps = 8 heads).
// ---------------------------------------------------------------------------
__global__ __launch_bounds__(256) void norm_rope_kernel(
    const float* __restrict__ q, const float* __restrict__ k,
    __half* __restrict__ qh, __half* __restrict__ kh,
    const float* __restrict__ rope,
    const float* __restrict__ wq, const float* __restrict__ wk)
{
    __shared__ float cs_s[128], sn_s[128];
    const int row = blockIdx.x;
    const int s   = row & (SSEQ - 1);
    const int t   = threadIdx.x;

    if (t < 128) {
        float fr = rope[s * HD + t];
        float sn, cs;
        sincosf(fr, &sn, &cs);
        cs_s[t] = cs;
        sn_s[t] = sn;
    }
    __syncthreads();

    const int w    = t >> 5;
    const int lane = t & 31;
    const int h    = blockIdx.y * 8 + w;
    const int d4   = lane * 4;
    const size_t idx = (size_t)row * DM + h * HD + d4;
    const bool lo  = (lane < 16);   // d4 < 64

    float4 c4 = *(float4*)&cs_s[d4];
    float4 s4 = *(float4*)&sn_s[d4];

    #pragma unroll
    for (int which = 0; which < 2; which++) {
        const float* src = which ? k : q;
        __half* dst      = which ? kh : qh;
        const float* wn  = which ? wk : wq;

        float4 x = *(const float4*)(src + idx);
        float ss = x.x*x.x + x.y*x.y + x.z*x.z + x.w*x.w;
        #pragma unroll
        for (int o = 16; o > 0; o >>= 1)
            ss += __shfl_xor_sync(0xffffffffu, ss, o);
        float rs = rsqrtf(ss * (1.f/128.f) + 1e-6f);
        float4 wv = *(const float4*)(wn + d4);
        float xn0 = x.x * rs * wv.x;
        float xn1 = x.y * rs * wv.y;
        float xn2 = x.z * rs * wv.z;
        float xn3 = x.w * rs * wv.w;
        float p0 = __shfl_xor_sync(0xffffffffu, xn0, 16);
        float p1 = __shfl_xor_sync(0xffffffffu, xn1, 16);
        float p2 = __shfl_xor_sync(0xffffffffu, xn2, 16);
        float p3 = __shfl_xor_sync(0xffffffffu, xn3, 16);
        float r0 = lo ? -p0 : p0;
        float r1 = lo ? -p1 : p1;
        float r2 = lo ? -p2 : p2;
        float r3 = lo ? -p3 : p3;
        __half2 h0 = __floats2half2_rn(xn0 * c4.x + r0 * s4.x,
                                       xn1 * c4.y + r1 * s4.y);
        __half2 h1 = __floats2half2_rn(xn2 * c4.z + r2 * s4.z,
                                       xn3 * c4.w + r3 * s4.w);
        uint2 o = {*(uint32_t*)&h0, *(uint32_t*)&h1};
        *(uint2*)(dst + idx) = o;
    }
}

// ---------------------------------------------------------------------------
// fp16 flash attention, FA2 register softmax; Q fragments hoisted to registers.
// ---------------------------------------------------------------------------
#define STH 136
#define STB (STH*2)
#define ATT_SMEM ((64 + 128 + 128) * STH * 2)   // 87040

__global__ __launch_bounds__(128) void attn_kernel(
    const __half* __restrict__ Q, const __half* __restrict__ K,
    const __half* __restrict__ V, __half* __restrict__ O)
{
    extern __shared__ char smraw[];
    __half* Qh = (__half*)smraw;
    __half* Kh = Qh + 64 * STH;
    __half* Vh = Kh + 128 * STH;
    const uint32_t sQ = smem_u32(Qh);
    const uint32_t sK = smem_u32(Kh);
    const uint32_t sV = smem_u32(Vh);

    const int t    = threadIdx.x;
    const int lane = t & 31;
    const int w    = t >> 5;
    const int qd   = lane >> 2;
    const int qk   = lane & 3;
    const int wm   = w * 16;

    const int qt = blockIdx.x;
    const int bh = blockIdx.y;
    const int b  = bh / NH;
    const int h  = bh % NH;
    const size_t base = (size_t)b * SSEQ * DM + (size_t)h * HD;
    const __half* qb = Q + base;
    const __half* kb = K + base;
    const __half* vb = V + base;
    const int q0 = qt * 64;

    const int l7   = lane & 7;
    const int arow = ((lane >> 3) & 1) * 8 + l7;
    const int akh  = (lane >> 4) * 8;
    const uint32_t aQ = sQ + (uint32_t)(wm + arow) * STB + (uint32_t)akh * 2u;
    const int bnr  = (lane >> 4) * 8 + l7;
    const int bkh  = ((lane >> 3) & 1) * 8;
    const uint32_t aK = sK + (uint32_t)bnr * STB + (uint32_t)bkh * 2u;
    const uint32_t aV = sV + (uint32_t)arow * STB + (uint32_t)((lane >> 4) * 8) * 2u;

    // Load Q tile
    #pragma unroll
    for (int it = 0; it < 8; it++) {
        const int f   = t + it * 128;
        const int row = f >> 4;
        const int c8  = (f & 15) * 8;
        uint4 u = *(const uint4*)(qb + (size_t)(q0 + row) * DM + c8);
        *(uint4*)(Qh + row * STH + c8) = u;
    }
    __syncthreads();

    // Hoist Q fragments (loop-invariant)
    uint32_t qf[8][4];
    #pragma unroll
    for (int ks = 0; ks < 8; ks++)
        ldsm_x4(qf[ks][0], qf[ks][1], qf[ks][2], qf[ks][3],
                aQ + (uint32_t)ks * 32u);

    float o[16][4];
    #pragma unroll
    for (int ni = 0; ni < 16; ni++)
        #pragma unroll
        for (int j = 0; j < 4; j++) o[ni][j] = 0.f;

    float m0 = -1e30f, m1 = -1e30f, l0 = 0.f, l1 = 0.f;
    const float scale2 = 0.12751744f;   // (1/sqrt(128)) * log2(e)

    for (int kt = 0; kt < 8; kt++) {
        const int k0s = kt * 128;
        __syncthreads();   // prior sub-iters' K/V reads complete

        #pragma unroll
        for (int it = 0; it < 16; it++) {
            const int f   = t + it * 128;
            const int row = f >> 4;
            const int c8  = (f & 15) * 8;
            const size_t g = (size_t)(k0s + row) * DM + c8;
            *(uint4*)(Kh + row * STH + c8) = *(const uint4*)(kb + g);
            *(uint4*)(Vh + row * STH + c8) = *(const uint4*)(vb + g);
        }
        __syncthreads();

        #pragma unroll
        for (int half = 0; half < 2; half++) {
            const uint32_t hrow = (uint32_t)(half * 64) * STB;

            float cs[8][4];
            #pragma unroll
            for (int ni = 0; ni < 8; ni++)
                #pragma unroll
                for (int j = 0; j < 4; j++) cs[ni][j] = 0.f;

            #pragma unroll
            for (int ks = 0; ks < 8; ks++) {
                const uint32_t koff = (uint32_t)ks * 32u;
                #pragma unroll
                for (int p = 0; p < 4; p++) {
                    uint32_t b0, b1, b2, b3;
                    ldsm_x4(b0, b1, b2, b3, aK + hrow + (uint32_t)(p * 16) * STB + koff);
                    mma_f16(cs[2*p],   qf[ks][0], qf[ks][1], qf[ks][2], qf[ks][3], b0, b1);
                    mma_f16(cs[2*p+1], qf[ks][0], qf[ks][1], qf[ks][2], qf[ks][3], b2, b3);
                }
            }
            #pragma unroll
            for (int ni = 0; ni < 8; ni++) {
                cs[ni][0] *= scale2; cs[ni][1] *= scale2;
                cs[ni][2] *= scale2; cs[ni][3] *= scale2;
            }

            float t0 = -1e30f, t1 = -1e30f;
            #pragma unroll
            for (int ni = 0; ni < 8; ni++) {
                t0 = fmaxf(t0, fmaxf(cs[ni][0], cs[ni][1]));
                t1 = fmaxf(t1, fmaxf(cs[ni][2], cs[ni][3]));
            }
            t0 = fmaxf(t0, __shfl_xor_sync(0xffffffffu, t0, 1));
            t0 = fmaxf(t0, __shfl_xor_sync(0xffffffffu, t0, 2));
            t1 = fmaxf(t1, __shfl_xor_sync(0xffffffffu, t1, 1));
            t1 = fmaxf(t1, __shfl_xor_sync(0xffffffffu, t1, 2));
            const float mn0 = fmaxf(m0, t0);
            const float mn1 = fmaxf(m1, t1);
            const float al0 = fexp2(m0 - mn0);
            const float al1 = fexp2(m1 - mn1);

            uint32_t plo[8], phi[8];
            float ps0 = 0.f, ps1 = 0.f;
            #pragma unroll
            for (int ni = 0; ni < 8; ni++) {
                __half2 d0 = __floats2half2_rn(cs[ni][0] - mn0, cs[ni][1] - mn0);
                __half2 d1 = __floats2half2_rn(cs[ni][2] - mn1, cs[ni][3] - mn1);
                plo[ni] = h2exp2_bits(*(uint32_t*)&d0);
                phi[ni] = h2exp2_bits(*(uint32_t*)&d1);
                __half2 p0 = *(__half2*)&plo[ni];
                __half2 p1 = *(__half2*)&phi[ni];
                ps0 += __low2float(p0) + __high2float(p0);
                ps1 += __low2float(p1) + __high2float(p1);
            }
            ps0 += __shfl_xor_sync(0xffffffffu, ps0, 1);
            ps0 += __shfl_xor_sync(0xffffffffu, ps0, 2);
            ps1 += __shfl_xor_sync(0xffffffffu, ps1, 1);
            ps1 += __shfl_xor_sync(0xffffffffu, ps1, 2);
            l0 = l0 * al0 + ps0;
            l1 = l1 * al1 + ps1;
            m0 = mn0;
            m1 = mn1;

            #pragma unroll
            for (int ni = 0; ni < 16; ni++) {
                o[ni][0] *= al0; o[ni][1] *= al0;
                o[ni][2] *= al1; o[ni][3] *= al1;
            }

            #pragma unroll
            for (int kc = 0; kc < 4; kc++) {
                const uint32_t a0 = plo[2*kc],   a1 = phi[2*kc];
                const uint32_t a2 = plo[2*kc+1], a3 = phi[2*kc+1];
                const uint32_t vro = hrow + (uint32_t)(kc * 16) * STB;
                #pragma unroll
                for (int np = 0; np < 8; np++) {
                    uint32_t b0, b1, b2, b3;
                    ldsm_x4_t(b0, b1, b2, b3, aV + vro + (uint32_t)np * 32u);
                    mma_f16(o[2*np],   a0, a1, a2, a3, b0, b1);
                    mma_f16(o[2*np+1], a0, a1, a2, a3, b2, b3);
                }
            }
        }
    }

    const float inv0 = 1.f / l0;
    const float inv1 = 1.f / l1;
    #pragma unroll
    for (int ni = 0; ni < 16; ni++) {
        const int col = ni * 8 + 2 * qk;
        __half2 h0 = __floats2half2_rn(o[ni][0] * inv0, o[ni][1] * inv0);
        __half2 h1 = __floats2half2_rn(o[ni][2] * inv1, o[ni][3] * inv1);
        *(__half2*)(O + base + (size_t)(q0 + wm + qd)     * DM + col) = h0;
        *(__half2*)(O + base + (size_t)(q0 + wm + qd + 8) * DM + col) = h1;
    }
}

// ---------------------------------------------------------------------------
extern "C" void kernel_launch(void* const* d_in, const int* in_sizes, int n_in,
                              void* d_out, int out_size)
{
    const float* hidden = (const float*)d_in[0];
    const float* rope   = (const float*)d_in[1];
    const float* Wq     = (const float*)d_in[2];
    const float* Wk     = (const float*)d_in[3];
    const float* Wv     = (const float*)d_in[4];
    const float* Wo     = (const float*)d_in[5];
    const float* nqw    = (const float*)d_in[6];
    const float* nkw    = (const float*)d_in[7];
    float* out = (float*)d_out;

    float *q, *k;
    __half *xh, *kh, *vh, *aoh, *wqh, *wkh, *wvh, *woh;
    cudaGetSymbolAddress((void**)&q,   g_q);
    cudaGetSymbolAddress((void**)&k,   g_k);
    cudaGetSymbolAddress((void**)&xh,  g_xh);
    cudaGetSymbolAddress((void**)&kh,  g_kh);
    cudaGetSymbolAddress((void**)&vh,  g_vh);
    cudaGetSymbolAddress((void**)&aoh, g_aoh);
    cudaGetSymbolAddress((void**)&wqh, g_wqh);
    cudaGetSymbolAddress((void**)&wkh, g_wkh);
    cudaGetSymbolAddress((void**)&wvh, g_wvh);
    cudaGetSymbolAddress((void**)&woh, g_woh);

    const int nX4 = MROWS * DM / 4;
    const int nW4 = DM * DM / 4;
    cvt_f32_f16<<<(nX4/2 + 255) / 256, 256>>>(hidden, xh, nX4/2);
    cvt4_f32_f16<<<(2 * nW4 + 255) / 256, 256>>>(Wq, Wk, Wv, Wo,
                                                 wqh, wkh, wvh, woh, nW4);

    cudaFuncSetAttribute(f16_gemm_kernel<false>, cudaFuncAttributeMaxDynamicSharedMemorySize, GEMM_SMEM);
    cudaFuncSetAttribute(f16_gemm_kernel<true>,  cudaFuncAttributeMaxDynamicSharedMemorySize, GEMM_SMEM);
    cudaFuncSetAttribute(attn_kernel, cudaFuncAttributeMaxDynamicSharedMemorySize, ATT_SMEM);

    // Zero the output early (needed by the reducing Wo GEMM)
    zero_f32<<<(nX4 + 255) / 256, 256>>>(out, nX4);

    // Fused QKV projection: q,k -> fp32; v -> fp16 directly
    f16_gemm_kernel<false><<<dim3(72, 16, 1), 256, GEMM_SMEM>>>(xh, wqh, wkh, wvh, q, k, vh);

    // Norm+RoPE: q,k fp32 -> fp16 (q-hat into xh)
    norm_rope_kernel<<<dim3(MROWS, NH/8), 256>>>(q, k, xh, kh, rope, nqw, nkw);

    attn_kernel<<<dim3(SSEQ/64, BB*NH), 128, ATT_SMEM>>>(xh, kh, vh, aoh);

    // Output projection, k-split 2, atomic-add epilogue
    f16_gemm_kernel<true><<<dim3(24, 16, 2), 256, GEMM_SMEM>>>(aoh, woh, woh, woh, out, out, aoh);
}

// round 13
// speedup vs baseline: 2.8428x; 1.0147x over previous
#include <cuda_runtime.h>
#include <cuda_fp16.h>
#include <math.h>
#include <stdint.h>

#define DM 3072
#define BB 2
#define SSEQ 1024
#define NH 24
#define HD 128
#define MROWS (BB*SSEQ)   // 2048

// Scratch (device globals: no allocations allowed)
__device__ float  g_q[MROWS*DM];
__device__ float  g_k[MROWS*DM];
__device__ __half g_xh[MROWS*DM];   // hidden fp16, later reused as q-hat fp16
__device__ __half g_kh[MROWS*DM];
__device__ __half g_vh[MROWS*DM];
__device__ __half g_aoh[MROWS*DM];
__device__ __half g_wqh[DM*DM];
__device__ __half g_wkh[DM*DM];
__device__ __half g_wvh[DM*DM];
__device__ __half g_woh[DM*DM];

__device__ __forceinline__ uint32_t smem_u32(const void* p) {
    uint32_t a;
    asm("{ .reg .u64 t; cvta.to.shared.u64 t, %1; cvt.u32.u64 %0, t; }"
        : "=r"(a) : "l"(p));
    return a;
}

__device__ __forceinline__ float fexp2(float x) {
    float y;
    asm("ex2.approx.f32 %0, %1;" : "=f"(y) : "f"(x));
    return y;
}

__device__ __forceinline__ uint32_t h2exp2_bits(uint32_t x) {
    uint32_t y;
    asm("ex2.approx.f16x2 %0, %1;" : "=r"(y) : "r"(x));
    return y;
}

__device__ __forceinline__ void mma_f16(float c[4],
    uint32_t a0, uint32_t a1, uint32_t a2, uint32_t a3,
    uint32_t b0, uint32_t b1)
{
    asm volatile(
        "mma.sync.aligned.m16n8k16.row.col.f32.f16.f16.f32 "
        "{%0,%1,%2,%3}, {%4,%5,%6,%7}, {%8,%9}, {%0,%1,%2,%3};"
        : "+f"(c[0]), "+f"(c[1]), "+f"(c[2]), "+f"(c[3])
        : "r"(a0), "r"(a1), "r"(a2), "r"(a3), "r"(b0), "r"(b1));
}

__device__ __forceinline__ void ldsm_x4(
    uint32_t& r0, uint32_t& r1, uint32_t& r2, uint32_t& r3, uint32_t addr)
{
    asm volatile("ldmatrix.sync.aligned.m8n8.x4.shared.b16 {%0,%1,%2,%3}, [%4];"
        : "=r"(r0), "=r"(r1), "=r"(r2), "=r"(r3) : "r"(addr));
}

__device__ __forceinline__ void ldsm_x4_t(
    uint32_t& r0, uint32_t& r1, uint32_t& r2, uint32_t& r3, uint32_t addr)
{
    asm volatile("ldmatrix.sync.aligned.m8n8.x4.trans.shared.b16 {%0,%1,%2,%3}, [%4];"
        : "=r"(r0), "=r"(r1), "=r"(r2), "=r"(r3) : "r"(addr));
}

__device__ __forceinline__ void cp_async16(uint32_t saddr, const void* gptr) {
    asm volatile("cp.async.cg.shared.global [%0], [%1], 16;"
        :: "r"(saddr), "l"(gptr) : "memory");
}
#define CP_COMMIT() asm volatile("cp.async.commit_group;" ::: "memory")
#define CP_WAIT3()  asm volatile("cp.async.wait_group 3;" ::: "memory")
#define CP_WAIT1()  asm volatile("cp.async.wait_group 1;" ::: "memory")

__device__ __forceinline__ void red_add_f32(float* p, float v) {
    asm volatile("red.global.add.f32 [%0], %1;" :: "l"(p), "f"(v) : "memory");
}

// ---------------------------------------------------------------------------
// fp32 -> fp16 conversions (2-element ILP)
// ---------------------------------------------------------------------------
__global__ __launch_bounds__(256) void cvt_f32_f16(
    const float* __restrict__ src, __half* __restrict__ dst, int n4h)
{
    int i = blockIdx.x * blockDim.x + threadIdx.x;
    if (i < n4h) {
        float4 v0 = ((const float4*)src)[i];
        float4 v1 = ((const float4*)src)[i + n4h];
        __half2 a0 = __floats2half2_rn(v0.x, v0.y);
        __half2 a1 = __floats2half2_rn(v0.z, v0.w);
        __half2 b0 = __floats2half2_rn(v1.x, v1.y);
        __half2 b1 = __floats2half2_rn(v1.z, v1.w);
        uint2 o0 = {*(uint32_t*)&a0, *(uint32_t*)&a1};
        uint2 o1 = {*(uint32_t*)&b0, *(uint32_t*)&b1};
        ((uint2*)dst)[i]       = o0;
        ((uint2*)dst)[i + n4h] = o1;
    }
}

__global__ __launch_bounds__(256) void cvt4_f32_f16(
    const float* __restrict__ s0, const float* __restrict__ s1,
    const float* __restrict__ s2, const float* __restrict__ s3,
    __half* __restrict__ d0, __half* __restrict__ d1,
    __half* __restrict__ d2, __half* __restrict__ d3, int n4)
{
    int base = blockIdx.x * blockDim.x + threadIdx.x;
    #pragma unroll
    for (int r = 0; r < 2; r++) {
        int i = base + r * ((4 * n4) / 2);
        int which = i / n4;
        int j = i - which * n4;
        const float* s = (which == 0) ? s0 : (which == 1) ? s1 : (which == 2) ? s2 : s3;
        __half* d      = (which == 0) ? d0 : (which == 1) ? d1 : (which == 2) ? d2 : d3;
        float4 v = ((const float4*)s)[j];
        __half2 h0 = __floats2half2_rn(v.x, v.y);
        __half2 h1 = __floats2half2_rn(v.z, v.w);
        uint2 o = {*(uint32_t*)&h0, *(uint32_t*)&h1};
        ((uint2*)d)[j] = o;
    }
}

__global__ __launch_bounds__(256) void zero_f32(float* __restrict__ p, int n4)
{
    int i = blockIdx.x * blockDim.x + threadIdx.x;
    if (i < n4) {
        float4 z = {0.f, 0.f, 0.f, 0.f};
        ((float4*)p)[i] = z;
    }
}

// ---------------------------------------------------------------------------
// fp16 GEMM, cp.async 5-stage pipeline, one sync per k-tile.
// k-range split by blockIdx.z. REDUCE: fp32 red.add epilogue.
// ---------------------------------------------------------------------------
#define STAGEB 20480
#define NSTAGE 5
#define GEMM_SMEM (NSTAGE * STAGEB)   // 102400

template<bool REDUCE>
__global__ __launch_bounds__(256, 2) void f16_gemm_kernel(
    const __half* __restrict__ X,
    const __half* __restrict__ Wa, const __half* __restrict__ Wb, const __half* __restrict__ Wc,
    float* __restrict__ Ya, float* __restrict__ Yb, __half* __restrict__ Yc)
{
    extern __shared__ char smraw[];
    const uint32_t smb = smem_u32(smraw);

    const int t    = threadIdx.x;
    const int lane = t & 31;
    const int w    = t >> 5;
    const int warp_m = (w >> 1) * 32;
    const int warp_n = (w & 1) * 64;
    const int bx   = blockIdx.x;
    const int wsel = bx / 24;
    const __half* W = (wsel == 0) ? Wa : ((wsel == 1) ? Wb : Wc);
    const int bm = blockIdx.y * 128;
    const int bn = (bx - wsel * 24) * 128;

    const int nkt = (DM / 32) / gridDim.z;       // 96 or 32
    const int kh0 = blockIdx.z * nkt * 32;

    const int arow = t >> 1;
    const int kh16 = (t & 1) * 16;
    const __half* xp = X + (size_t)(bm + arow) * DM + kh0 + kh16;
    const __half* wp = W + (size_t)(bn + arow) * DM + kh0 + kh16;
    const uint32_t srow = (uint32_t)arow * 80u + (uint32_t)kh16 * 2u;

    const int l7 = lane & 7;
    const int aArow = warp_m + ((lane >> 3) & 1) * 8 + l7;
    const int aAkh  = (lane >> 4) * 8;
    uint32_t offA[2];
    #pragma unroll
    for (int mi = 0; mi < 2; mi++)
        offA[mi] = (uint32_t)(aArow + mi * 16) * 80u + (uint32_t)aAkh * 2u;
    const int aBn  = warp_n + (lane >> 4) * 8 + l7;
    const int aBkh = ((lane >> 3) & 1) * 8;
    uint32_t offB[4];
    #pragma unroll
    for (int np = 0; np < 4; np++)
        offB[np] = 10240u + (uint32_t)(aBn + np * 16) * 80u + (uint32_t)aBkh * 2u;

    float c[2][8][4];
    #pragma unroll
    for (int mi = 0; mi < 2; mi++)
        #pragma unroll
        for (int ni = 0; ni < 8; ni++)
            #pragma unroll
            for (int j = 0; j < 4; j++) c[mi][ni][j] = 0.f;

    const int qd = lane >> 2;
    const int qk = lane & 3;

    #define ISSUE(kt_, buf_) do { \
        const uint32_t sa = smb + (uint32_t)(buf_) * STAGEB + srow; \
        const __half* xg = xp + (kt_) * 32; \
        const __half* wg = wp + (kt_) * 32; \
        cp_async16(sa,           xg); \
        cp_async16(sa + 16u,     xg + 8); \
        cp_async16(sa + 10240u,      wg); \
        cp_async16(sa + 10240u + 16u, wg + 8); \
    } while (0)

    ISSUE(0, 0); CP_COMMIT();
    ISSUE(1, 1); CP_COMMIT();
    ISSUE(2, 2); CP_COMMIT();
    ISSUE(3, 3); CP_COMMIT();

    int buf = 0, ib = 4;
    for (int kt = 0; kt < nkt; kt++) {
        CP_WAIT3();        // stage kt landed
        __syncthreads();   // all threads past wait; compute of kt-1 done

        const int nk = kt + 4;
        if (nk < nkt) {
            ISSUE(nk, ib); // buffer of stage kt-1, reads done
        }
        CP_COMMIT();

        const uint32_t st = smb + (uint32_t)buf * STAGEB;
        #pragma unroll
        for (int ks = 0; ks < 2; ks++) {
            const uint32_t koff = (uint32_t)ks * 32u;
            uint32_t a[2][4];
            ldsm_x4(a[0][0], a[0][1], a[0][2], a[0][3], st + offA[0] + koff);
            ldsm_x4(a[1][0], a[1][1], a[1][2], a[1][3], st + offA[1] + koff);
            #pragma unroll
            for (int np = 0; np < 4; np++) {
                uint32_t b0, b1, b2, b3;
                ldsm_x4(b0, b1, b2, b3, st + offB[np] + koff);
                mma_f16(c[0][2*np],   a[0][0], a[0][1], a[0][2], a[0][3], b0, b1);
                mma_f16(c[1][2*np],   a[1][0], a[1][1], a[1][2], a[1][3], b0, b1);
                mma_f16(c[0][2*np+1], a[0][0], a[0][1], a[0][2], a[0][3], b2, b3);
                mma_f16(c[1][2*np+1], a[1][0], a[1][1], a[1][2], a[1][3], b2, b3);
            }
        }
        buf = (buf + 1 == NSTAGE) ? 0 : buf + 1;
        ib  = (ib  + 1 == NSTAGE) ? 0 : ib + 1;
    }
    #undef ISSUE

    if (REDUCE) {
        float* Y = Ya;
        #pragma unroll
        for (int mi = 0; mi < 2; mi++) {
            #pragma unroll
            for (int ni = 0; ni < 8; ni++) {
                const int row = bm + warp_m + mi*16 + qd;
                const int col = bn + warp_n + ni*8 + qk*2;
                float* p0 = Y + (size_t)row * DM + col;
                float* p1 = Y + (size_t)(row + 8) * DM + col;
                red_add_f32(p0,     c[mi][ni][0]);
                red_add_f32(p0 + 1, c[mi][ni][1]);
                red_add_f32(p1,     c[mi][ni][2]);
                red_add_f32(p1 + 1, c[mi][ni][3]);
            }
        }
    } else if (wsel < 2) {
        float* Y = wsel ? Yb : Ya;
        #pragma unroll
        for (int mi = 0; mi < 2; mi++) {
            #pragma unroll
            for (int ni = 0; ni < 8; ni++) {
                const int row = bm + warp_m + mi*16 + qd;
                const int col = bn + warp_n + ni*8 + qk*2;
                float2 v0 = {c[mi][ni][0], c[mi][ni][1]};
                float2 v1 = {c[mi][ni][2], c[mi][ni][3]};
                *(float2*)(Y + (size_t)row * DM + col)       = v0;
                *(float2*)(Y + (size_t)(row + 8) * DM + col) = v1;
            }
        }
    } else {
        #pragma unroll
        for (int mi = 0; mi < 2; mi++) {
            #pragma unroll
            for (int ni = 0; ni < 8; ni++) {
                const int row = bm + warp_m + mi*16 + qd;
                const int col = bn + warp_n + ni*8 + qk*2;
                __half2 h0 = __floats2half2_rn(c[mi][ni][0], c[mi][ni][1]);
                __half2 h1 = __floats2half2_rn(c[mi][ni][2], c[mi][ni][3]);
                *(__half2*)(Yc + (size_t)row * DM + col)       = h0;
                *(__half2*)(Yc + (size_t)(row + 8) * DM + col) = h1;
            }
        }
    }
}

// ---------------------------------------------------------------------------
// Fused RMSNorm + RoPE v2 (unchanged from R12).
// ---------------------------------------------------------------------------
__global__ __launch_bounds__(256) void norm_rope_kernel(
    const float* __restrict__ q, const float* __restrict__ k,
    __half* __restrict__ qh, __half* __restrict__ kh,
    const float* __restrict__ rope,
    const float* __restrict__ wq, const float* __restrict__ wk)
{
    __shared__ float cs_s[128], sn_s[128];
    const int row = blockIdx.x;
    const int s   = row & (SSEQ - 1);
    const int t   = threadIdx.x;

    if (t < 128) {
        float fr = rope[s * HD + t];
        float sn, cs;
        sincosf(fr, &sn, &cs);
        cs_s[t] = cs;
        sn_s[t] = sn;
    }
    __syncthreads();

    const int w    = t >> 5;
    const int lane = t & 31;
    const int h    = blockIdx.y * 8 + w;
    const int d4   = lane * 4;
    const size_t idx = (size_t)row * DM + h * HD + d4;
    const bool lo  = (lane < 16);

    float4 c4 = *(float4*)&cs_s[d4];
    float4 s4 = *(float4*)&sn_s[d4];

    #pragma unroll
    for (int which = 0; which < 2; which++) {
        const float* src = which ? k : q;
        __half* dst      = which ? kh : qh;
        const float* wn  = which ? wk : wq;

        float4 x = *(const float4*)(src + idx);
        float ss = x.x*x.x + x.y*x.y + x.z*x.z + x.w*x.w;
        #pragma unroll
        for (int o = 16; o > 0; o >>= 1)
            ss += __shfl_xor_sync(0xffffffffu, ss, o);
        float rs = rsqrtf(ss * (1.f/128.f) + 1e-6f);
        float4 wv = *(const float4*)(wn + d4);
        float xn0 = x.x * rs * wv.x;
        float xn1 = x.y * rs * wv.y;
        float xn2 = x.z * rs * wv.z;
        float xn3 = x.w * rs * wv.w;
        float p0 = __shfl_xor_sync(0xffffffffu, xn0, 16);
        float p1 = __shfl_xor_sync(0xffffffffu, xn1, 16);
        float p2 = __shfl_xor_sync(0xffffffffu, xn2, 16);
        float p3 = __shfl_xor_sync(0xffffffffu, xn3, 16);
        float r0 = lo ? -p0 : p0;
        float r1 = lo ? -p1 : p1;
        float r2 = lo ? -p2 : p2;
        float r3 = lo ? -p3 : p3;
        __half2 h0 = __floats2half2_rn(xn0 * c4.x + r0 * s4.x,
                                       xn1 * c4.y + r1 * s4.y);
        __half2 h1 = __floats2half2_rn(xn2 * c4.z + r2 * s4.z,
                                       xn3 * c4.w + r3 * s4.w);
        uint2 o = {*(uint32_t*)&h0, *(uint32_t*)&h1};
        *(uint2*)(dst + idx) = o;
    }
}

// ---------------------------------------------------------------------------
// fp16 flash attention, FA2 register softmax, cp.async double-buffered
// 64-key K/V tiles. Q fragments hoisted. 128 threads (4 warps).
// Smem: Qh[64], K[2][64], V[2][64], rows of 136 halves (272B). 87040B.
// ---------------------------------------------------------------------------
#define STH 136
#define STB (STH*2)
#define ATT_SMEM ((64 + 128 + 128) * STH * 2)   // 87040

__global__ __launch_bounds__(128) void attn_kernel(
    const __half* __restrict__ Q, const __half* __restrict__ K,
    const __half* __restrict__ V, __half* __restrict__ O)
{
    extern __shared__ char smraw[];
    __half* Qh = (__half*)smraw;
    const uint32_t sQ = smem_u32(Qh);
    const uint32_t sK0 = sQ + 64u * STB;     // K buf0
    const uint32_t sK1 = sQ + 128u * STB;    // K buf1
    const uint32_t sV0 = sQ + 192u * STB;    // V buf0
    const uint32_t sV1 = sQ + 256u * STB;    // V buf1

    const int t    = threadIdx.x;
    const int lane = t & 31;
    const int w    = t >> 5;
    const int qd   = lane >> 2;
    const int qk   = lane & 3;
    const int wm   = w * 16;

    const int qt = blockIdx.x;
    const int bh = blockIdx.y;
    const int b  = bh / NH;
    const int h  = bh % NH;
    const size_t base = (size_t)b * SSEQ * DM + (size_t)h * HD;
    const __half* qb = Q + base;
    const __half* kb = K + base;
    const __half* vb = V + base;
    const int q0 = qt * 64;

    // per-thread cp.async row/chunk mapping: f = t + it*128, row=f>>4, ch=f&15
    // (8 its cover 64 rows x 16 chunks of 16B)

    // fragment address bases
    const int l7   = lane & 7;
    const int arow = ((lane >> 3) & 1) * 8 + l7;
    const int akh  = (lane >> 4) * 8;
    const uint32_t aQ = sQ + (uint32_t)(wm + arow) * STB + (uint32_t)akh * 2u;
    const int bnr  = (lane >> 4) * 8 + l7;
    const int bkh  = ((lane >> 3) & 1) * 8;
    const uint32_t fK0 = sK0 + (uint32_t)bnr * STB + (uint32_t)bkh * 2u;
    const uint32_t fK1 = sK1 + (uint32_t)bnr * STB + (uint32_t)bkh * 2u;
    const uint32_t voff = (uint32_t)arow * STB + (uint32_t)((lane >> 4) * 8) * 2u;
    const uint32_t fV0 = sV0 + voff;
    const uint32_t fV1 = sV1 + voff;

    #define ATT_ISSUE(kt_, kbuf_, vbuf_) do { \
        const int k0_ = (kt_) * 64; \
        _Pragma("unroll") \
        for (int it = 0; it < 8; it++) { \
            const int f   = t + it * 128; \
            const int row = f >> 4; \
            const int ch  = f & 15; \
            const size_t g = (size_t)(k0_ + row) * DM + ch * 8; \
            const uint32_t so = (uint32_t)row * STB + (uint32_t)ch * 16u; \
            cp_async16((kbuf_) + so, kb + g); \
            cp_async16((vbuf_) + so, vb + g); \
        } \
    } while (0)

    // Start K/V tiles 0,1 before anything else
    ATT_ISSUE(0, sK0, sV0); CP_COMMIT();
    ATT_ISSUE(1, sK1, sV1); CP_COMMIT();

    // Load Q tile (plain LDG->STS)
    #pragma unroll
    for (int it = 0; it < 8; it++) {
        const int f   = t + it * 128;
        const int row = f >> 4;
        const int c8  = (f & 15) * 8;
        uint4 u = *(const uint4*)(qb + (size_t)(q0 + row) * DM + c8);
        *(uint4*)(Qh + row * STH + c8) = u;
    }
    __syncthreads();

    // Hoist Q fragments
    uint32_t qf[8][4];
    #pragma unroll
    for (int ks = 0; ks < 8; ks++)
        ldsm_x4(qf[ks][0], qf[ks][1], qf[ks][2], qf[ks][3],
                aQ + (uint32_t)ks * 32u);

    float o[16][4];
    #pragma unroll
    for (int ni = 0; ni < 16; ni++)
        #pragma unroll
        for (int j = 0; j < 4; j++) o[ni][j] = 0.f;

    float m0 = -1e30f, m1 = -1e30f, l0 = 0.f, l1 = 0.f;
    const float scale2 = 0.12751744f;   // (1/sqrt(128)) * log2(e)

    for (int kt = 0; kt < 16; kt++) {
        CP_WAIT1();        // tile kt landed (tile kt+1 may be in flight)
        __syncthreads();   // all threads past their wait

        const uint32_t fK = (kt & 1) ? fK1 : fK0;
        const uint32_t fV = (kt & 1) ? fV1 : fV0;

        // Scores: S[16x64] = Q_warp @ K^T
        float cs[8][4];
        #pragma unroll
        for (int ni = 0; ni < 8; ni++)
            #pragma unroll
            for (int j = 0; j < 4; j++) cs[ni][j] = 0.f;

        #pragma unroll
        for (int ks = 0; ks < 8; ks++) {
            const uint32_t koff = (uint32_t)ks * 32u;
            #pragma unroll
            for (int p = 0; p < 4; p++) {
                uint32_t b0, b1, b2, b3;
                ldsm_x4(b0, b1, b2, b3, fK + (uint32_t)(p * 16) * STB + koff);
                mma_f16(cs[2*p],   qf[ks][0], qf[ks][1], qf[ks][2], qf[ks][3], b0, b1);
                mma_f16(cs[2*p+1], qf[ks][0], qf[ks][1], qf[ks][2], qf[ks][3], b2, b3);
            }
        }
        #pragma unroll
        for (int ni = 0; ni < 8; ni++) {
            cs[ni][0] *= scale2; cs[ni][1] *= scale2;
            cs[ni][2] *= scale2; cs[ni][3] *= scale2;
        }

        // Warp-local online softmax (rows qd, qd+8)
        float t0 = -1e30f, t1 = -1e30f;
        #pragma unroll
        for (int ni = 0; ni < 8; ni++) {
            t0 = fmaxf(t0, fmaxf(cs[ni][0], cs[ni][1]));
            t1 = fmaxf(t1, fmaxf(cs[ni][2], cs[ni][3]));
        }
        t0 = fmaxf(t0, __shfl_xor_sync(0xffffffffu, t0, 1));
        t0 = fmaxf(t0, __shfl_xor_sync(0xffffffffu, t0, 2));
        t1 = fmaxf(t1, __shfl_xor_sync(0xffffffffu, t1, 1));
        t1 = fmaxf(t1, __shfl_xor_sync(0xffffffffu, t1, 2));
        const float mn0 = fmaxf(m0, t0);
        const float mn1 = fmaxf(m1, t1);
        const float al0 = fexp2(m0 - mn0);
        const float al1 = fexp2(m1 - mn1);

        uint32_t plo[8], phi[8];
        float ps0 = 0.f, ps1 = 0.f;
        #pragma unroll
        for (int ni = 0; ni < 8; ni++) {
            __half2 d0 = __floats2half2_rn(cs[ni][0] - mn0, cs[ni][1] - mn0);
            __half2 d1 = __floats2half2_rn(cs[ni][2] - mn1, cs[ni][3] - mn1);
            plo[ni] = h2exp2_bits(*(uint32_t*)&d0);
            phi[ni] = h2exp2_bits(*(uint32_t*)&d1);
            __half2 p0 = *(__half2*)&plo[ni];
            __half2 p1 = *(__half2*)&phi[ni];
            ps0 += __low2float(p0) + __high2float(p0);
            ps1 += __low2float(p1) + __high2float(p1);
        }
        ps0 += __shfl_xor_sync(0xffffffffu, ps0, 1);
        ps0 += __shfl_xor_sync(0xffffffffu, ps0, 2);
        ps1 += __shfl_xor_sync(0xffffffffu, ps1, 1);
        ps1 += __shfl_xor_sync(0xffffffffu, ps1, 2);
        l0 = l0 * al0 + ps0;
        l1 = l1 * al1 + ps1;
        m0 = mn0;
        m1 = mn1;

        #pragma unroll
        for (int ni = 0; ni < 16; ni++) {
            o[ni][0] *= al0; o[ni][1] *= al0;
            o[ni][2] *= al1; o[ni][3] *= al1;
        }

        // PV: O[16x128] += P[16x64] @ V[64x128]
        #pragma unroll
        for (int kc = 0; kc < 4; kc++) {
            const uint32_t a0 = plo[2*kc],   a1 = phi[2*kc];
            const uint32_t a2 = plo[2*kc+1], a3 = phi[2*kc+1];
            const uint32_t vro = (uint32_t)(kc * 16) * STB;
            #pragma unroll
            for (int np = 0; np < 8; np++) {
                uint32_t b0, b1, b2, b3;
                ldsm_x4_t(b0, b1, b2, b3, fV + vro + (uint32_t)np * 32u);
                mma_f16(o[2*np],   a0, a1, a2, a3, b0, b1);
                mma_f16(o[2*np+1], a0, a1, a2, a3, b2, b3);
            }
        }

        __syncthreads();   // all warps done reading buf kt&1
        if (kt + 2 < 16) {
            if (kt & 1) { ATT_ISSUE(kt + 2, sK1, sV1); }
            else        { ATT_ISSUE(kt + 2, sK0, sV0); }
        }
        CP_COMMIT();       // unconditional: keeps group counting uniform
    }
    #undef ATT_ISSUE

    const float inv0 = 1.f / l0;
    const float inv1 = 1.f / l1;
    #pragma unroll
    for (int ni = 0; ni < 16; ni++) {
        const int col = ni * 8 + 2 * qk;
        __half2 h0 = __floats2half2_rn(o[ni][0] * inv0, o[ni][1] * inv0);
        __half2 h1 = __floats2half2_rn(o[ni][2] * inv1, o[ni][3] * inv1);
        *(__half2*)(O + base + (size_t)(q0 + wm + qd)     * DM + col) = h0;
        *(__half2*)(O + base + (size_t)(q0 + wm + qd + 8) * DM + col) = h1;
    }
}

// ---------------------------------------------------------------------------
extern "C" void kernel_launch(void* const* d_in, const int* in_sizes, int n_in,
                              void* d_out, int out_size)
{
    const float* hidden = (const float*)d_in[0];
    const float* rope   = (const float*)d_in[1];
    const float* Wq     = (const float*)d_in[2];
    const float* Wk     = (const float*)d_in[3];
    const float* Wv     = (const float*)d_in[4];
    const float* Wo     = (const float*)d_in[5];
    const float* nqw    = (const float*)d_in[6];
    const float* nkw    = (const float*)d_in[7];
    float* out = (float*)d_out;

    float *q, *k;
    __half *xh, *kh, *vh, *aoh, *wqh, *wkh, *wvh, *woh;
    cudaGetSymbolAddress((void**)&q,   g_q);
    cudaGetSymbolAddress((void**)&k,   g_k);
    cudaGetSymbolAddress((void**)&xh,  g_xh);
    cudaGetSymbolAddress((void**)&kh,  g_kh);
    cudaGetSymbolAddress((void**)&vh,  g_vh);
    cudaGetSymbolAddress((void**)&aoh, g_aoh);
    cudaGetSymbolAddress((void**)&wqh, g_wqh);
    cudaGetSymbolAddress((void**)&wkh, g_wkh);
    cudaGetSymbolAddress((void**)&wvh, g_wvh);
    cudaGetSymbolAddress((void**)&woh, g_woh);

    const int nX4 = MROWS * DM / 4;
    const int nW4 = DM * DM / 4;
    zero_f32<<<(nX4 + 255) / 256, 256>>>(out, nX4);
    cvt_f32_f16<<<(nX4/2 + 255) / 256, 256>>>(hidden, xh, nX4/2);
    cvt4_f32_f16<<<(2 * nW4 + 255) / 256, 256>>>(Wq, Wk, Wv, Wo,
                                                 wqh, wkh, wvh, woh, nW4);

    cudaFuncSetAttribute(f16_gemm_kernel<false>, cudaFuncAttributeMaxDynamicSharedMemorySize, GEMM_SMEM);
    cudaFuncSetAttribute(f16_gemm_kernel<true>,  cudaFuncAttributeMaxDynamicSharedMemorySize, GEMM_SMEM);
    cudaFuncSetAttribute(attn_kernel, cudaFuncAttributeMaxDynamicSharedMemorySize, ATT_SMEM);

    // Fused QKV projection: q,k -> fp32; v -> fp16 directly
    f16_gemm_kernel<false><<<dim3(72, 16, 1), 256, GEMM_SMEM>>>(xh, wqh, wkh, wvh, q, k, vh);

    // Norm+RoPE: q,k fp32 -> fp16 (q-hat into xh)
    norm_rope_kernel<<<dim3(MROWS, NH/8), 256>>>(q, k, xh, kh, rope, nqw, nkw);

    attn_kernel<<<dim3(SSEQ/64, BB*NH), 128, ATT_SMEM>>>(xh, kh, vh, aoh);

    // Output projection, k-split 3, atomic-add epilogue
    f16_gemm_kernel<true><<<dim3(24, 16, 3), 256, GEMM_SMEM>>>(aoh, woh, woh, woh, out, out, aoh);
}